// round 1
// baseline (speedup 1.0000x reference)
#include <cuda_runtime.h>
#include <cuda_bf16.h>
#include <mma.h>
#include <math.h>

using namespace nvcuda;

// Problem constants
#define T_TOK   4096      // BATCH*SEQ
#define SEQLEN  2048
#define HID     2048
#define NQH     16
#define NKVH    8
#define HD      128
#define QKVW    6144      // 4096 (q+gate) + 1024 (k) + 1024 (v)

// Scratch (device globals — no allocation allowed)
__device__ float g_qkv[(size_t)T_TOK * QKVW];   // ~100.7 MB
__device__ float g_attn[(size_t)T_TOK * HID];   // ~33.5 MB

// ---------------------------------------------------------------------------
// TF32 wmma GEMM: C[M,N] (+colOff into ldc-wide C) = A[M,K] @ B[K,N]
// Block tile 128x128, K-step 32, 8 warps (2x4), each warp 64x32 (4x2 frags)
// ---------------------------------------------------------------------------
__global__ __launch_bounds__(256) void gemm_tf32(
    const float* __restrict__ A, const float* __restrict__ B,
    float* __restrict__ C, int M, int N, int K,
    int lda, int ldb, int ldc, int cColOff)
{
    __shared__ float As[128 * 40];   // [128][40] row-major (k contiguous), pad 40
    __shared__ float Bs[32 * 136];   // [32][136] row-major (n contiguous), pad 136

    const int m0 = blockIdx.y * 128;
    const int n0 = blockIdx.x * 128;
    const int tid = threadIdx.x;
    const int w   = tid >> 5;
    const int wm  = w & 1;        // 0..1 -> 64 rows each
    const int wn  = w >> 1;       // 0..3 -> 32 cols each

    wmma::fragment<wmma::accumulator, 16, 16, 8, float> acc[4][2];
#pragma unroll
    for (int i = 0; i < 4; i++)
#pragma unroll
        for (int j = 0; j < 2; j++)
            wmma::fill_fragment(acc[i][j], 0.0f);

    for (int k0 = 0; k0 < K; k0 += 32) {
        __syncthreads();
        // Load A tile 128x32 (1024 float4, 4 per thread)
#pragma unroll
        for (int t = 0; t < 4; t++) {
            int idx = tid + t * 256;
            int r = idx >> 3, c4 = (idx & 7) * 4;
            float4 v = *(const float4*)(A + (size_t)(m0 + r) * lda + k0 + c4);
            *(float4*)(As + r * 40 + c4) = v;
        }
        // Load B tile 32x128 (1024 float4, 4 per thread)
#pragma unroll
        for (int t = 0; t < 4; t++) {
            int idx = tid + t * 256;
            int r = idx >> 5, c4 = (idx & 31) * 4;
            float4 v = *(const float4*)(B + (size_t)(k0 + r) * ldb + n0 + c4);
            *(float4*)(Bs + r * 136 + c4) = v;
        }
        __syncthreads();

#pragma unroll
        for (int kk = 0; kk < 32; kk += 8) {
            wmma::fragment<wmma::matrix_a, 16, 16, 8, wmma::precision::tf32, wmma::row_major> af[4];
            wmma::fragment<wmma::matrix_b, 16, 16, 8, wmma::precision::tf32, wmma::row_major> bf[2];
#pragma unroll
            for (int i = 0; i < 4; i++) {
                wmma::load_matrix_sync(af[i], As + (wm * 64 + i * 16) * 40 + kk, 40);
#pragma unroll
                for (int t = 0; t < af[i].num_elements; t++)
                    af[i].x[t] = wmma::__float_to_tf32(af[i].x[t]);
            }
#pragma unroll
            for (int j = 0; j < 2; j++) {
                wmma::load_matrix_sync(bf[j], Bs + kk * 136 + wn * 32 + j * 16, 136);
#pragma unroll
                for (int t = 0; t < bf[j].num_elements; t++)
                    bf[j].x[t] = wmma::__float_to_tf32(bf[j].x[t]);
            }
#pragma unroll
            for (int i = 0; i < 4; i++)
#pragma unroll
                for (int j = 0; j < 2; j++)
                    wmma::mma_sync(acc[i][j], af[i], bf[j], acc[i][j]);
        }
    }

#pragma unroll
    for (int i = 0; i < 4; i++)
#pragma unroll
        for (int j = 0; j < 2; j++)
            wmma::store_matrix_sync(
                C + (size_t)(m0 + wm * 64 + i * 16) * ldc + cColOff + n0 + wn * 32 + j * 16,
                acc[i][j], ldc, wmma::mem_row_major);
}

// ---------------------------------------------------------------------------
// Per-(token, head) RMSNorm + partial RoPE (in-place on g_qkv)
// blockIdx.x = token t (0..4095), blockIdx.y = head (0..15 Q, 16..23 K)
// ---------------------------------------------------------------------------
__global__ __launch_bounds__(128) void normrope_kernel(
    float* __restrict__ qkv,
    const float* __restrict__ qnw, const float* __restrict__ knw,
    const int* __restrict__ positions)
{
    const int t  = blockIdx.x;
    const int hh = blockIdx.y;
    const int d  = threadIdx.x;

    float* vec;
    const float* w;
    if (hh < NQH) { vec = qkv + (size_t)t * QKVW + hh * 256;               w = qnw; }
    else          { vec = qkv + (size_t)t * QKVW + 4096 + (hh - NQH) * HD; w = knw; }

    float x = vec[d];

    __shared__ float sred[4];
    __shared__ float sv[128];
    int lane = d & 31, wrp = d >> 5;
    float ss = x * x;
#pragma unroll
    for (int o = 16; o > 0; o >>= 1) ss += __shfl_xor_sync(0xffffffffu, ss, o);
    if (lane == 0) sred[wrp] = ss;
    __syncthreads();
    float tot = sred[0] + sred[1] + sred[2] + sred[3];
    float r = rsqrtf(tot * (1.0f / 128.0f) + 1e-6f);
    float y = x * r * (1.0f + w[d]);

    sv[d] = y;
    __syncthreads();

    float out = y;
    if (d < 32) {
        int j = d & 15;
        float inv = powf(10000000.0f, -(float)j * (1.0f / 16.0f));
        float ang = (float)positions[t] * inv;
        float c = cosf(ang), s = sinf(ang);
        int base = (d < 16) ? d : (d - 16);
        float x1 = sv[base];
        float x2 = sv[base + 16];
        out = (d < 16) ? (x1 * c - x2 * s) : (x1 * s + x2 * c);
    }
    vec[d] = out;
}

// ---------------------------------------------------------------------------
// SIMT fp32 flash attention. BQ=BK=64, 256 threads.
// grid: (32 qtiles [reversed], 16 heads, 2 batch)
// Epilogue fuses sigmoid(gate).
// ---------------------------------------------------------------------------
#define AT_BQ 64
#define AT_BK 64
#define LQ 129
#define LV 132
#define LS 68

__global__ __launch_bounds__(256) void attn_kernel(
    const float* __restrict__ qkv,
    const int*   __restrict__ amask,
    float*       __restrict__ aout)
{
    extern __shared__ float sm[];
    float* Qs   = sm;                       // 64*129
    float* Ks   = Qs + 64 * LQ;             // 64*129
    float* Vs   = Ks + 64 * LQ;             // 64*132
    float* Ss   = Vs + 64 * LV;             // 64*68
    float* red  = Ss + 64 * LS;             // 256
    float* rowm = red + 256;                // 64
    float* rowl = rowm + 64;                // 64
    float* rowa = rowl + 64;                // 64

    const int qt = (int)gridDim.x - 1 - (int)blockIdx.x;  // heavy tiles first
    const int h  = blockIdx.y;
    const int b  = blockIdx.z;
    const int kvh = h >> 1;

    const float* Qb = qkv + (size_t)b * SEQLEN * QKVW + h * 256;
    const float* Gb = Qb + 128;
    const float* Kb = qkv + (size_t)b * SEQLEN * QKVW + 4096 + kvh * HD;
    const float* Vb = qkv + (size_t)b * SEQLEN * QKVW + 5120 + kvh * HD;
    const int*   mk = amask + b * SEQLEN;

    const int tid = threadIdx.x;
    const int ty = tid >> 4, tx = tid & 15;

    // Load Q tile (rows qt*64..+63, 128 cols)
    for (int i = tid; i < 64 * 32; i += 256) {
        int r = i >> 5, c4 = (i & 31) * 4;
        float4 v = *(const float4*)(Qb + (size_t)(qt * 64 + r) * QKVW + c4);
        Qs[r * LQ + c4]     = v.x;
        Qs[r * LQ + c4 + 1] = v.y;
        Qs[r * LQ + c4 + 2] = v.z;
        Qs[r * LQ + c4 + 3] = v.w;
    }
    if (tid < 64) { rowm[tid] = -1e30f; rowl[tid] = 0.0f; }

    float o[4][8];
#pragma unroll
    for (int i = 0; i < 4; i++)
#pragma unroll
        for (int dd = 0; dd < 8; dd++) o[i][dd] = 0.0f;

    const float scale = 0.08838834764831845f;  // 1/sqrt(128)
    __syncthreads();

    for (int kt = 0; kt <= qt; kt++) {
        // Load K and V tiles
        for (int i = tid; i < 64 * 32; i += 256) {
            int r = i >> 5, c4 = (i & 31) * 4;
            float4 kv4 = *(const float4*)(Kb + (size_t)(kt * 64 + r) * QKVW + c4);
            Ks[r * LQ + c4]     = kv4.x;
            Ks[r * LQ + c4 + 1] = kv4.y;
            Ks[r * LQ + c4 + 2] = kv4.z;
            Ks[r * LQ + c4 + 3] = kv4.w;
            float4 vv4 = *(const float4*)(Vb + (size_t)(kt * 64 + r) * QKVW + c4);
            *(float4*)(Vs + r * LV + c4) = vv4;
        }
        __syncthreads();

        // S = Q K^T (each thread 4x4)
        float acc[4][4];
#pragma unroll
        for (int i = 0; i < 4; i++)
#pragma unroll
            for (int j = 0; j < 4; j++) acc[i][j] = 0.0f;

#pragma unroll 4
        for (int d = 0; d < 128; d++) {
            float qv[4], kv[4];
#pragma unroll
            for (int i = 0; i < 4; i++) qv[i] = Qs[(ty * 4 + i) * LQ + d];
#pragma unroll
            for (int j = 0; j < 4; j++) kv[j] = Ks[(tx * 4 + j) * LQ + d];
#pragma unroll
            for (int i = 0; i < 4; i++)
#pragma unroll
                for (int j = 0; j < 4; j++) acc[i][j] += qv[i] * kv[j];
        }

        // scale + causal mask + attention_mask -> Ss
#pragma unroll
        for (int i = 0; i < 4; i++) {
            int sq = qt * 64 + ty * 4 + i;
#pragma unroll
            for (int j = 0; j < 4; j++) {
                int sk = kt * 64 + tx * 4 + j;
                float val = acc[i][j] * scale;
                if (sk > sq || mk[sk] == 0) val = -1e30f;
                Ss[(ty * 4 + i) * LS + tx * 4 + j] = val;
            }
        }
        __syncthreads();

        // Row max (4 threads per row, 16 cols each)
        {
            int r = tid & 63, part = tid >> 6;
            float pm = -1e30f;
#pragma unroll
            for (int j = 0; j < 16; j++) pm = fmaxf(pm, Ss[r * LS + part * 16 + j]);
            red[part * 64 + r] = pm;
        }
        __syncthreads();
        if (tid < 64) {
            int r = tid;
            float mnew = fmaxf(fmaxf(red[r], red[64 + r]), fmaxf(red[128 + r], red[192 + r]));
            mnew = fmaxf(mnew, rowm[r]);
            rowa[r] = __expf(rowm[r] - mnew);
            rowm[r] = mnew;
        }
        __syncthreads();

        // Exponentiate + partial sums
        {
            int r = tid & 63, part = tid >> 6;
            float m = rowm[r];
            float psum = 0.0f;
#pragma unroll
            for (int j = 0; j < 16; j++) {
                float p = __expf(Ss[r * LS + part * 16 + j] - m);
                Ss[r * LS + part * 16 + j] = p;
                psum += p;
            }
            red[part * 64 + r] = psum;
        }
        __syncthreads();
        if (tid < 64) {
            int r = tid;
            rowl[r] = rowl[r] * rowa[r] + red[r] + red[64 + r] + red[128 + r] + red[192 + r];
        }

        // Rescale O and accumulate P @ V
        float al[4];
#pragma unroll
        for (int i = 0; i < 4; i++) al[i] = rowa[ty * 4 + i];
#pragma unroll
        for (int i = 0; i < 4; i++)
#pragma unroll
            for (int dd = 0; dd < 8; dd++) o[i][dd] *= al[i];

#pragma unroll 2
        for (int c = 0; c < 64; c++) {
            float p[4];
#pragma unroll
            for (int i = 0; i < 4; i++) p[i] = Ss[(ty * 4 + i) * LS + c];
            float v[8];
#pragma unroll
            for (int dd = 0; dd < 8; dd++) v[dd] = Vs[c * LV + tx * 8 + dd];
#pragma unroll
            for (int i = 0; i < 4; i++)
#pragma unroll
                for (int dd = 0; dd < 8; dd++) o[i][dd] += p[i] * v[dd];
        }
        __syncthreads();
    }

    // Epilogue: normalize, sigmoid-gate, write
#pragma unroll
    for (int i = 0; i < 4; i++) {
        int r = ty * 4 + i;
        int s = qt * 64 + r;
        float inv = 1.0f / rowl[r];
#pragma unroll
        for (int dd = 0; dd < 8; dd++) {
            int dcol = tx * 8 + dd;
            float g = Gb[(size_t)s * QKVW + dcol];
            float val = o[i][dd] * inv * (1.0f / (1.0f + __expf(-g)));
            aout[((size_t)b * SEQLEN + s) * HID + h * HD + dcol] = val;
        }
    }
}

// ---------------------------------------------------------------------------
extern "C" void kernel_launch(void* const* d_in, const int* in_sizes, int n_in,
                              void* d_out, int out_size)
{
    const float* x     = (const float*)d_in[0];
    const int*   amask = (const int*)  d_in[1];
    const int*   pos   = (const int*)  d_in[2];
    const float* Wq    = (const float*)d_in[3];
    const float* Wk    = (const float*)d_in[4];
    const float* Wv    = (const float*)d_in[5];
    const float* Wo    = (const float*)d_in[6];
    const float* qnw   = (const float*)d_in[7];
    const float* knw   = (const float*)d_in[8];
    float* out = (float*)d_out;

    void* p_qkv_v;  cudaGetSymbolAddress(&p_qkv_v,  g_qkv);
    void* p_attn_v; cudaGetSymbolAddress(&p_attn_v, g_attn);
    float* qkv  = (float*)p_qkv_v;
    float* attn = (float*)p_attn_v;

    dim3 blk(256);

    // 1) Fused QKV+gate projections into g_qkv [T, 6144]
    gemm_tf32<<<dim3(32, 32), blk>>>(x, Wq, qkv, T_TOK, 4096, HID, HID, 4096, QKVW, 0);
    gemm_tf32<<<dim3(8,  32), blk>>>(x, Wk, qkv, T_TOK, 1024, HID, HID, 1024, QKVW, 4096);
    gemm_tf32<<<dim3(8,  32), blk>>>(x, Wv, qkv, T_TOK, 1024, HID, HID, 1024, QKVW, 5120);

    // 2) QK RMSNorm + RoPE (in-place)
    normrope_kernel<<<dim3(T_TOK, NQH + NKVH), 128>>>(qkv, qnw, knw, pos);

    // 3) Flash attention + sigmoid gate
    size_t smem_bytes = (size_t)(64 * LQ * 2 + 64 * LV + 64 * LS + 256 + 192) * sizeof(float);
    cudaFuncSetAttribute(attn_kernel, cudaFuncAttributeMaxDynamicSharedMemorySize,
                         (int)smem_bytes);
    attn_kernel<<<dim3(SEQLEN / AT_BQ, NQH, 2), blk, smem_bytes>>>(qkv, amask, attn);

    // 4) Output projection -> d_out
    gemm_tf32<<<dim3(16, 32), blk>>>(attn, Wo, out, T_TOK, HID, HID, HID, HID, HID, 0);
}

// round 2
// speedup vs baseline: 1.2063x; 1.2063x over previous
#include <cuda_runtime.h>
#include <cuda_bf16.h>
#include <mma.h>
#include <math.h>

using namespace nvcuda;

// Problem constants
#define T_TOK   4096      // BATCH*SEQ
#define SEQLEN  2048
#define HID     2048
#define NQH     16
#define NKVH    8
#define HD      128
#define QKVW    6144      // 4096 (q+gate) + 1024 (k) + 1024 (v)

// Scratch (device globals — no allocation allowed)
__device__ float g_qkv[(size_t)T_TOK * QKVW];   // ~100.7 MB
__device__ float g_attn[(size_t)T_TOK * HID];   // ~33.5 MB

__device__ __forceinline__ float to_tf32(float x) {
    float r;
    asm("cvt.rna.tf32.f32 %0, %1;" : "=f"(r) : "f"(x));
    return r;
}

__device__ __forceinline__ void cpa16(float* smem_dst, const float* gmem_src) {
    unsigned s = (unsigned)__cvta_generic_to_shared(smem_dst);
    asm volatile("cp.async.cg.shared.global [%0], [%1], 16;" :: "r"(s), "l"(gmem_src));
}
#define CPA_COMMIT asm volatile("cp.async.commit_group;")
#define CPA_WAIT0  asm volatile("cp.async.wait_group 0;")

// ---------------------------------------------------------------------------
// TF32 wmma GEMM, 2-stage cp.async pipeline.
// Block tile 128x128, K-step 32, 8 warps (2x4), each warp 64x32 (4x2 frags)
// ---------------------------------------------------------------------------
__global__ __launch_bounds__(256, 2) void gemm_tf32(
    const float* __restrict__ A, const float* __restrict__ B,
    float* __restrict__ C, int M, int N, int K,
    int lda, int ldb, int ldc, int cColOff)
{
    __shared__ float As[2][128 * 40];
    __shared__ float Bs[2][32 * 136];

    const int m0 = blockIdx.y * 128;
    const int n0 = blockIdx.x * 128;
    const int tid = threadIdx.x;
    const int w   = tid >> 5;
    const int wm  = w & 1;
    const int wn  = w >> 1;

    wmma::fragment<wmma::accumulator, 16, 16, 8, float> acc[4][2];
#pragma unroll
    for (int i = 0; i < 4; i++)
#pragma unroll
        for (int j = 0; j < 2; j++)
            wmma::fill_fragment(acc[i][j], 0.0f);

    const int KT = K >> 5;

    // Prefetch tile 0
    {
#pragma unroll
        for (int t = 0; t < 4; t++) {
            int idx = tid + t * 256;
            int r = idx >> 3, c4 = (idx & 7) * 4;
            cpa16(&As[0][r * 40 + c4], A + (size_t)(m0 + r) * lda + c4);
        }
#pragma unroll
        for (int t = 0; t < 4; t++) {
            int idx = tid + t * 256;
            int r = idx >> 5, c4 = (idx & 31) * 4;
            cpa16(&Bs[0][r * 136 + c4], B + (size_t)r * ldb + n0 + c4);
        }
        CPA_COMMIT;
    }

    for (int kt = 0; kt < KT; kt++) {
        CPA_WAIT0;
        __syncthreads();
        const int buf = kt & 1;

        if (kt + 1 < KT) {
            const int k0 = (kt + 1) << 5;
            const int nb = buf ^ 1;
#pragma unroll
            for (int t = 0; t < 4; t++) {
                int idx = tid + t * 256;
                int r = idx >> 3, c4 = (idx & 7) * 4;
                cpa16(&As[nb][r * 40 + c4], A + (size_t)(m0 + r) * lda + k0 + c4);
            }
#pragma unroll
            for (int t = 0; t < 4; t++) {
                int idx = tid + t * 256;
                int r = idx >> 5, c4 = (idx & 31) * 4;
                cpa16(&Bs[nb][r * 136 + c4], B + (size_t)(k0 + r) * ldb + n0 + c4);
            }
            CPA_COMMIT;
        }

#pragma unroll
        for (int kk = 0; kk < 32; kk += 8) {
            wmma::fragment<wmma::matrix_a, 16, 16, 8, wmma::precision::tf32, wmma::row_major> af[4];
            wmma::fragment<wmma::matrix_b, 16, 16, 8, wmma::precision::tf32, wmma::row_major> bf[2];
#pragma unroll
            for (int i = 0; i < 4; i++) {
                wmma::load_matrix_sync(af[i], &As[buf][(wm * 64 + i * 16) * 40 + kk], 40);
#pragma unroll
                for (int t = 0; t < af[i].num_elements; t++)
                    af[i].x[t] = wmma::__float_to_tf32(af[i].x[t]);
            }
#pragma unroll
            for (int j = 0; j < 2; j++) {
                wmma::load_matrix_sync(bf[j], &Bs[buf][kk * 136 + wn * 32 + j * 16], 136);
#pragma unroll
                for (int t = 0; t < bf[j].num_elements; t++)
                    bf[j].x[t] = wmma::__float_to_tf32(bf[j].x[t]);
            }
#pragma unroll
            for (int i = 0; i < 4; i++)
#pragma unroll
                for (int j = 0; j < 2; j++)
                    wmma::mma_sync(acc[i][j], af[i], bf[j], acc[i][j]);
        }
    }

#pragma unroll
    for (int i = 0; i < 4; i++)
#pragma unroll
        for (int j = 0; j < 2; j++)
            wmma::store_matrix_sync(
                C + (size_t)(m0 + wm * 64 + i * 16) * ldc + cColOff + n0 + wn * 32 + j * 16,
                acc[i][j], ldc, wmma::mem_row_major);
}

// ---------------------------------------------------------------------------
// Per-(token, head) RMSNorm + partial RoPE (in-place on g_qkv)
// ---------------------------------------------------------------------------
__global__ __launch_bounds__(128) void normrope_kernel(
    float* __restrict__ qkv,
    const float* __restrict__ qnw, const float* __restrict__ knw,
    const int* __restrict__ positions)
{
    const int t  = blockIdx.x;
    const int hh = blockIdx.y;
    const int d  = threadIdx.x;

    float* vec;
    const float* w;
    if (hh < NQH) { vec = qkv + (size_t)t * QKVW + hh * 256;               w = qnw; }
    else          { vec = qkv + (size_t)t * QKVW + 4096 + (hh - NQH) * HD; w = knw; }

    float x = vec[d];

    __shared__ float sred[4];
    __shared__ float sv[128];
    int lane = d & 31, wrp = d >> 5;
    float ss = x * x;
#pragma unroll
    for (int o = 16; o > 0; o >>= 1) ss += __shfl_xor_sync(0xffffffffu, ss, o);
    if (lane == 0) sred[wrp] = ss;
    __syncthreads();
    float tot = sred[0] + sred[1] + sred[2] + sred[3];
    float r = rsqrtf(tot * (1.0f / 128.0f) + 1e-6f);
    float y = x * r * (1.0f + w[d]);

    sv[d] = y;
    __syncthreads();

    float out = y;
    if (d < 32) {
        int j = d & 15;
        float inv = powf(10000000.0f, -(float)j * (1.0f / 16.0f));
        float ang = (float)positions[t] * inv;
        float c = cosf(ang), s = sinf(ang);
        int base = (d < 16) ? d : (d - 16);
        float x1 = sv[base];
        float x2 = sv[base + 16];
        out = (d < 16) ? (x1 * c - x2 * s) : (x1 * s + x2 * c);
    }
    vec[d] = out;
}

// ---------------------------------------------------------------------------
// Tensor-core (tf32 wmma) flash attention. BQ=BK=64, 256 threads, 8 warps.
// Online softmax SIMT on smem S tile; O accumulator merged in smem via
// wmma accumulator load/store. Epilogue fuses sigmoid(gate).
// grid: (32 qtiles [reversed], 16 heads, 2 batch)
// ---------------------------------------------------------------------------
#define LQ2 132   // stride for Q/K/V/O tiles (132 % 32 = 4 -> conflict-friendly)
#define LS2 68    // stride for S tile

__global__ __launch_bounds__(256) void attn_kernel2(
    const float* __restrict__ qkv,
    const int*   __restrict__ amask,
    float*       __restrict__ aout)
{
    extern __shared__ float sm2[];
    float* Qs   = sm2;                 // 64*132
    float* Ks   = Qs + 64 * LQ2;       // 64*132
    float* Vs   = Ks + 64 * LQ2;       // 64*132
    float* Os   = Vs + 64 * LQ2;       // 64*132
    float* Ss   = Os + 64 * LQ2;       // 64*68
    float* red  = Ss + 64 * LS2;       // 256
    float* rowm = red + 256;           // 64
    float* rowl = rowm + 64;           // 64
    float* rowa = rowl + 64;           // 64

    const int qt = (int)gridDim.x - 1 - (int)blockIdx.x;  // heavy tiles first
    const int h  = blockIdx.y;
    const int b  = blockIdx.z;
    const int kvh = h >> 1;

    const float* Qb = qkv + (size_t)b * SEQLEN * QKVW + h * 256;
    const float* Gb = Qb + 128;
    const float* Kb = qkv + (size_t)b * SEQLEN * QKVW + 4096 + kvh * HD;
    const float* Vb = Kb + 1024;
    const int*   mk = amask + b * SEQLEN;

    const int tid = threadIdx.x;
    const int w   = tid >> 5;
    const int wr  = w & 3;     // 4 row-groups of 16
    const int wc  = w >> 2;    // 2 column halves

    // Load Q tile (pre-rounded to tf32) + zero O accumulator
    for (int i = tid; i < 64 * 32; i += 256) {
        int r = i >> 5, c4 = (i & 31) * 4;
        float4 v = *(const float4*)(Qb + (size_t)(qt * 64 + r) * QKVW + c4);
        float* dq = Qs + r * LQ2 + c4;
        dq[0] = to_tf32(v.x); dq[1] = to_tf32(v.y);
        dq[2] = to_tf32(v.z); dq[3] = to_tf32(v.w);
        float4 z = make_float4(0.f, 0.f, 0.f, 0.f);
        *(float4*)(Os + r * LQ2 + c4) = z;
    }
    if (tid < 64) { rowm[tid] = -1e30f; rowl[tid] = 0.0f; }
    __syncthreads();

    const float scale = 0.08838834764831845f;  // 1/sqrt(128)

    for (int kt = 0; kt <= qt; kt++) {
        // Load K, V tiles (pre-rounded to tf32)
        for (int i = tid; i < 64 * 32; i += 256) {
            int r = i >> 5, c4 = (i & 31) * 4;
            float4 k4 = *(const float4*)(Kb + (size_t)(kt * 64 + r) * QKVW + c4);
            float* dk = Ks + r * LQ2 + c4;
            dk[0] = to_tf32(k4.x); dk[1] = to_tf32(k4.y);
            dk[2] = to_tf32(k4.z); dk[3] = to_tf32(k4.w);
            float4 v4 = *(const float4*)(Vb + (size_t)(kt * 64 + r) * QKVW + c4);
            float* dv = Vs + r * LQ2 + c4;
            dv[0] = to_tf32(v4.x); dv[1] = to_tf32(v4.y);
            dv[2] = to_tf32(v4.z); dv[3] = to_tf32(v4.w);
        }
        __syncthreads();

        // S = Q K^T  (each warp: 16 rows x 32 cols, K along d=128)
        {
            wmma::fragment<wmma::accumulator, 16, 16, 8, float> sacc[2];
            wmma::fill_fragment(sacc[0], 0.0f);
            wmma::fill_fragment(sacc[1], 0.0f);
#pragma unroll
            for (int kk = 0; kk < 128; kk += 8) {
                wmma::fragment<wmma::matrix_a, 16, 16, 8, wmma::precision::tf32, wmma::row_major> af;
                wmma::load_matrix_sync(af, Qs + wr * 16 * LQ2 + kk, LQ2);
#pragma unroll
                for (int j = 0; j < 2; j++) {
                    wmma::fragment<wmma::matrix_b, 16, 16, 8, wmma::precision::tf32, wmma::col_major> bf;
                    wmma::load_matrix_sync(bf, Ks + (wc * 32 + j * 16) * LQ2 + kk, LQ2);
                    wmma::mma_sync(sacc[j], af, bf, sacc[j]);
                }
            }
            wmma::store_matrix_sync(Ss + wr * 16 * LS2 + wc * 32,      sacc[0], LS2, wmma::mem_row_major);
            wmma::store_matrix_sync(Ss + wr * 16 * LS2 + wc * 32 + 16, sacc[1], LS2, wmma::mem_row_major);
        }
        __syncthreads();

        // Pass 1: scale + mask, partial row max (4 threads/row)
        {
            int r = tid & 63, part = tid >> 6;
            int sq = qt * 64 + r;
            float pm = -1e30f;
#pragma unroll
            for (int j = 0; j < 16; j++) {
                int col = part * 16 + j;
                int sk = kt * 64 + col;
                float val = Ss[r * LS2 + col] * scale;
                if (sk > sq || mk[sk] == 0) val = -1e30f;
                Ss[r * LS2 + col] = val;
                pm = fmaxf(pm, val);
            }
            red[part * 64 + r] = pm;
        }
        __syncthreads();
        if (tid < 64) {
            float mnew = fmaxf(fmaxf(red[tid], red[64 + tid]),
                               fmaxf(red[128 + tid], red[192 + tid]));
            mnew = fmaxf(mnew, rowm[tid]);
            rowa[tid] = __expf(rowm[tid] - mnew);
            rowm[tid] = mnew;
        }
        __syncthreads();

        // Pass 2: exponentiate (round P to tf32), partial sums
        {
            int r = tid & 63, part = tid >> 6;
            float m = rowm[r];
            float psum = 0.0f;
#pragma unroll
            for (int j = 0; j < 16; j++) {
                float p = to_tf32(__expf(Ss[r * LS2 + part * 16 + j] - m));
                Ss[r * LS2 + part * 16 + j] = p;
                psum += p;
            }
            red[part * 64 + r] = psum;
        }
        __syncthreads();
        if (tid < 64)
            rowl[tid] = rowl[tid] * rowa[tid]
                      + red[tid] + red[64 + tid] + red[128 + tid] + red[192 + tid];
        // Rescale O accumulator by alpha
        for (int i = tid; i < 64 * 32; i += 256) {
            int r = i >> 5, c4 = (i & 31) * 4;
            float a = rowa[r];
            float4 o4 = *(float4*)(Os + r * LQ2 + c4);
            o4.x *= a; o4.y *= a; o4.z *= a; o4.w *= a;
            *(float4*)(Os + r * LQ2 + c4) = o4;
        }
        __syncthreads();

        // O += P V  (each warp: 16 rows x 64 d-cols, K along 64 keys)
        {
            wmma::fragment<wmma::accumulator, 16, 16, 8, float> oacc[4];
#pragma unroll
            for (int j = 0; j < 4; j++)
                wmma::load_matrix_sync(oacc[j], Os + wr * 16 * LQ2 + wc * 64 + j * 16,
                                       LQ2, wmma::mem_row_major);
#pragma unroll
            for (int kk = 0; kk < 64; kk += 8) {
                wmma::fragment<wmma::matrix_a, 16, 16, 8, wmma::precision::tf32, wmma::row_major> af;
                wmma::load_matrix_sync(af, Ss + wr * 16 * LS2 + kk, LS2);
#pragma unroll
                for (int j = 0; j < 4; j++) {
                    wmma::fragment<wmma::matrix_b, 16, 16, 8, wmma::precision::tf32, wmma::row_major> bf;
                    wmma::load_matrix_sync(bf, Vs + kk * LQ2 + wc * 64 + j * 16, LQ2);
                    wmma::mma_sync(oacc[j], af, bf, oacc[j]);
                }
            }
#pragma unroll
            for (int j = 0; j < 4; j++)
                wmma::store_matrix_sync(Os + wr * 16 * LQ2 + wc * 64 + j * 16, oacc[j],
                                        LQ2, wmma::mem_row_major);
        }
        __syncthreads();
    }

    // Epilogue: normalize, sigmoid-gate, write
    for (int i = tid; i < 64 * 32; i += 256) {
        int r = i >> 5, c4 = (i & 31) * 4;
        int s = qt * 64 + r;
        float inv = 1.0f / rowl[r];
        float4 g4 = *(const float4*)(Gb + (size_t)s * QKVW + c4);
        float4 o4 = *(float4*)(Os + r * LQ2 + c4);
        float4 res;
        res.x = o4.x * inv * (1.0f / (1.0f + __expf(-g4.x)));
        res.y = o4.y * inv * (1.0f / (1.0f + __expf(-g4.y)));
        res.z = o4.z * inv * (1.0f / (1.0f + __expf(-g4.z)));
        res.w = o4.w * inv * (1.0f / (1.0f + __expf(-g4.w)));
        *(float4*)(aout + ((size_t)b * SEQLEN + s) * HID + h * HD + c4) = res;
    }
}

// ---------------------------------------------------------------------------
extern "C" void kernel_launch(void* const* d_in, const int* in_sizes, int n_in,
                              void* d_out, int out_size)
{
    const float* x     = (const float*)d_in[0];
    const int*   amask = (const int*)  d_in[1];
    const int*   pos   = (const int*)  d_in[2];
    const float* Wq    = (const float*)d_in[3];
    const float* Wk    = (const float*)d_in[4];
    const float* Wv    = (const float*)d_in[5];
    const float* Wo    = (const float*)d_in[6];
    const float* qnw   = (const float*)d_in[7];
    const float* knw   = (const float*)d_in[8];
    float* out = (float*)d_out;

    void* p_qkv_v;  cudaGetSymbolAddress(&p_qkv_v,  g_qkv);
    void* p_attn_v; cudaGetSymbolAddress(&p_attn_v, g_attn);
    float* qkv  = (float*)p_qkv_v;
    float* attn = (float*)p_attn_v;

    dim3 blk(256);

    // 1) Fused QKV+gate projections into g_qkv [T, 6144]
    gemm_tf32<<<dim3(32, 32), blk>>>(x, Wq, qkv, T_TOK, 4096, HID, HID, 4096, QKVW, 0);
    gemm_tf32<<<dim3(8,  32), blk>>>(x, Wk, qkv, T_TOK, 1024, HID, HID, 1024, QKVW, 4096);
    gemm_tf32<<<dim3(8,  32), blk>>>(x, Wv, qkv, T_TOK, 1024, HID, HID, 1024, QKVW, 5120);

    // 2) QK RMSNorm + RoPE (in-place)
    normrope_kernel<<<dim3(T_TOK, NQH + NKVH), 128>>>(qkv, qnw, knw, pos);

    // 3) Tensor-core flash attention + sigmoid gate
    size_t smem_bytes = (size_t)(64 * LQ2 * 4 + 64 * LS2 + 256 + 192) * sizeof(float);
    cudaFuncSetAttribute(attn_kernel2, cudaFuncAttributeMaxDynamicSharedMemorySize,
                         (int)smem_bytes);
    attn_kernel2<<<dim3(SEQLEN / 64, NQH, 2), blk, smem_bytes>>>(qkv, amask, attn);

    // 4) Output projection -> d_out
    gemm_tf32<<<dim3(16, 32), blk>>>(attn, Wo, out, T_TOK, HID, HID, HID, HID, HID, 0);
}

// round 4
// speedup vs baseline: 1.3567x; 1.1246x over previous
#include <cuda_runtime.h>
#include <cuda_bf16.h>
#include <mma.h>
#include <math.h>

using namespace nvcuda;

// Problem constants
#define T_TOK   4096      // BATCH*SEQ
#define SEQLEN  2048
#define HID     2048
#define NQH     16
#define NKVH    8
#define HD      128
#define QKVW    6144      // 4096 (q+gate) + 1024 (k) + 1024 (v)

// Scratch (device globals — no allocation allowed)
__device__ float g_qkv[(size_t)T_TOK * QKVW];    // ~100.7 MB
__device__ float g_attn[(size_t)T_TOK * HID];    // ~33.5 MB (tf32-rounded attn out)
__device__ float g_x  [(size_t)T_TOK * HID];     // tf32-rounded x
__device__ float g_wq [(size_t)HID * 4096];
__device__ float g_wk [(size_t)HID * 1024];
__device__ float g_wv [(size_t)HID * 1024];
__device__ float g_wo [(size_t)HID * HID];

__device__ __forceinline__ float to_tf32(float x) {
    float r;
    asm("cvt.rna.tf32.f32 %0, %1;" : "=f"(r) : "f"(x));
    return r;
}

__device__ __forceinline__ void cpa16(float* smem_dst, const float* gmem_src) {
    unsigned s = (unsigned)__cvta_generic_to_shared(smem_dst);
    asm volatile("cp.async.cg.shared.global [%0], [%1], 16;" :: "r"(s), "l"(gmem_src));
}
#define CPA_COMMIT asm volatile("cp.async.commit_group;")
#define CPA_WAIT(n) asm volatile("cp.async.wait_group %0;" :: "n"(n))

// ---------------------------------------------------------------------------
// tf32 rounding copy (grid-stride float4)
// ---------------------------------------------------------------------------
__global__ __launch_bounds__(256) void round_copy(
    const float* __restrict__ in, float* __restrict__ out, int n4)
{
    for (int i = blockIdx.x * blockDim.x + threadIdx.x; i < n4; i += gridDim.x * blockDim.x) {
        float4 v = ((const float4*)in)[i];
        v.x = to_tf32(v.x); v.y = to_tf32(v.y);
        v.z = to_tf32(v.z); v.w = to_tf32(v.w);
        ((float4*)out)[i] = v;
    }
}

// ---------------------------------------------------------------------------
// TF32 wmma GEMM, 2-stage cp.async pipeline, pre-rounded inputs (no cvt).
// Block tile 128x128, K-step 32, 4 warps (2x2), each warp 64x64 (4x4 frags)
// ---------------------------------------------------------------------------
__global__ __launch_bounds__(128, 2) void gemm_tf32(
    const float* __restrict__ A, const float* __restrict__ B,
    float* __restrict__ C, int M, int N, int K,
    int lda, int ldb, int ldc, int cColOff)
{
    __shared__ float As[2][128 * 40];
    __shared__ float Bs[2][32 * 136];

    const int m0 = blockIdx.y * 128;
    const int n0 = blockIdx.x * 128;
    const int tid = threadIdx.x;
    const int w   = tid >> 5;
    const int wm  = w & 1;      // 2 row halves of 64
    const int wn  = w >> 1;     // 2 col halves of 64

    wmma::fragment<wmma::accumulator, 16, 16, 8, float> acc[4][4];
#pragma unroll
    for (int i = 0; i < 4; i++)
#pragma unroll
        for (int j = 0; j < 4; j++)
            wmma::fill_fragment(acc[i][j], 0.0f);

    const int KT = K >> 5;

    // Prefetch tile 0
#pragma unroll
    for (int t = 0; t < 8; t++) {
        int idx = tid + t * 128;
        int r = idx >> 3, c4 = (idx & 7) * 4;
        cpa16(&As[0][r * 40 + c4], A + (size_t)(m0 + r) * lda + c4);
    }
#pragma unroll
    for (int t = 0; t < 8; t++) {
        int idx = tid + t * 128;
        int r = idx >> 5, c4 = (idx & 31) * 4;
        cpa16(&Bs[0][r * 136 + c4], B + (size_t)r * ldb + n0 + c4);
    }
    CPA_COMMIT;

    for (int kt = 0; kt < KT; kt++) {
        CPA_WAIT(0);
        __syncthreads();
        const int buf = kt & 1;

        if (kt + 1 < KT) {
            const int k0 = (kt + 1) << 5;
            const int nb = buf ^ 1;
#pragma unroll
            for (int t = 0; t < 8; t++) {
                int idx = tid + t * 128;
                int r = idx >> 3, c4 = (idx & 7) * 4;
                cpa16(&As[nb][r * 40 + c4], A + (size_t)(m0 + r) * lda + k0 + c4);
            }
#pragma unroll
            for (int t = 0; t < 8; t++) {
                int idx = tid + t * 128;
                int r = idx >> 5, c4 = (idx & 31) * 4;
                cpa16(&Bs[nb][r * 136 + c4], B + (size_t)(k0 + r) * ldb + n0 + c4);
            }
            CPA_COMMIT;
        }

#pragma unroll
        for (int kk = 0; kk < 32; kk += 8) {
            wmma::fragment<wmma::matrix_a, 16, 16, 8, wmma::precision::tf32, wmma::row_major> af[4];
            wmma::fragment<wmma::matrix_b, 16, 16, 8, wmma::precision::tf32, wmma::row_major> bf[4];
#pragma unroll
            for (int i = 0; i < 4; i++)
                wmma::load_matrix_sync(af[i], &As[buf][(wm * 64 + i * 16) * 40 + kk], 40);
#pragma unroll
            for (int j = 0; j < 4; j++)
                wmma::load_matrix_sync(bf[j], &Bs[buf][kk * 136 + wn * 64 + j * 16], 136);
#pragma unroll
            for (int i = 0; i < 4; i++)
#pragma unroll
                for (int j = 0; j < 4; j++)
                    wmma::mma_sync(acc[i][j], af[i], bf[j], acc[i][j]);
        }
    }

#pragma unroll
    for (int i = 0; i < 4; i++)
#pragma unroll
        for (int j = 0; j < 4; j++)
            wmma::store_matrix_sync(
                C + (size_t)(m0 + wm * 64 + i * 16) * ldc + cColOff + n0 + wn * 64 + j * 16,
                acc[i][j], ldc, wmma::mem_row_major);
}

// ---------------------------------------------------------------------------
// Per-(token, head) RMSNorm + partial RoPE, then tf32-round q/k; also
// tf32-round v. In-place on g_qkv.
// grid: (4096, 32): hh 0..15 q, 16..23 k, 24..31 v
// ---------------------------------------------------------------------------
__global__ __launch_bounds__(128) void normrope_kernel(
    float* __restrict__ qkv,
    const float* __restrict__ qnw, const float* __restrict__ knw,
    const int* __restrict__ positions)
{
    const int t  = blockIdx.x;
    const int hh = blockIdx.y;
    const int d  = threadIdx.x;

    if (hh >= NQH + NKVH) {  // v heads: round only
        float* vec = qkv + (size_t)t * QKVW + 5120 + (hh - NQH - NKVH) * HD;
        vec[d] = to_tf32(vec[d]);
        return;
    }

    float* vec;
    const float* w;
    if (hh < NQH) { vec = qkv + (size_t)t * QKVW + hh * 256;               w = qnw; }
    else          { vec = qkv + (size_t)t * QKVW + 4096 + (hh - NQH) * HD; w = knw; }

    float x = vec[d];

    __shared__ float sred[4];
    __shared__ float sv[128];
    int lane = d & 31, wrp = d >> 5;
    float ss = x * x;
#pragma unroll
    for (int o = 16; o > 0; o >>= 1) ss += __shfl_xor_sync(0xffffffffu, ss, o);
    if (lane == 0) sred[wrp] = ss;
    __syncthreads();
    float tot = sred[0] + sred[1] + sred[2] + sred[3];
    float r = rsqrtf(tot * (1.0f / 128.0f) + 1e-6f);
    float y = x * r * (1.0f + w[d]);

    sv[d] = y;
    __syncthreads();

    float out = y;
    if (d < 32) {
        int j = d & 15;
        float inv = powf(10000000.0f, -(float)j * (1.0f / 16.0f));
        float ang = (float)positions[t] * inv;
        float c = cosf(ang), s = sinf(ang);
        int base = (d < 16) ? d : (d - 16);
        float x1 = sv[base];
        float x2 = sv[base + 16];
        out = (d < 16) ? (x1 * c - x2 * s) : (x1 * s + x2 * c);
    }
    vec[d] = to_tf32(out);
}

// ---------------------------------------------------------------------------
// Tensor-core (tf32 wmma) flash attention with cp.async double-buffered K/V.
// BQ=BK=64, 256 threads, 8 warps. Inputs pre-rounded to tf32.
// grid: (32 qtiles [reversed], 16 heads, 2 batch)
// ---------------------------------------------------------------------------
#define LQ2 132
#define LS2 68
#define TILE_F (64 * LQ2)

__global__ __launch_bounds__(256) void attn_kernel3(
    const float* __restrict__ qkv,
    const int*   __restrict__ amask,
    float*       __restrict__ aout)
{
    extern __shared__ float sm2[];
    float* Qs   = sm2;                  // 64*132
    float* Os   = Qs + TILE_F;          // 64*132
    float* Ks   = Os + TILE_F;          // 2 x 64*132
    float* Vs   = Ks + 2 * TILE_F;      // 2 x 64*132
    float* Ss   = Vs + 2 * TILE_F;      // 64*68
    float* red  = Ss + 64 * LS2;        // 256
    float* rowm = red + 256;            // 64
    float* rowl = rowm + 64;            // 64
    float* rowa = rowl + 64;            // 64

    const int qt = (int)gridDim.x - 1 - (int)blockIdx.x;
    const int h  = blockIdx.y;
    const int b  = blockIdx.z;
    const int kvh = h >> 1;

    const float* Qb = qkv + (size_t)b * SEQLEN * QKVW + h * 256;
    const float* Gb = Qb + 128;
    const float* Kb = qkv + (size_t)b * SEQLEN * QKVW + 4096 + kvh * HD;
    const float* Vb = Kb + 1024;
    const int*   mk = amask + b * SEQLEN;

    const int tid = threadIdx.x;
    const int w   = tid >> 5;
    const int wr  = w & 3;
    const int wc  = w >> 2;

    // Prefetch K/V tile 0
#pragma unroll
    for (int t = 0; t < 8; t++) {
        int idx = tid + t * 256;
        int r = idx >> 5, c4 = (idx & 31) * 4;
        size_t off = (size_t)r * QKVW + c4;
        cpa16(Ks + r * LQ2 + c4, Kb + off);
        cpa16(Vs + r * LQ2 + c4, Vb + off);
    }
    CPA_COMMIT;

    // Load Q tile (already tf32) + zero O
    for (int i = tid; i < 64 * 32; i += 256) {
        int r = i >> 5, c4 = (i & 31) * 4;
        float4 v = *(const float4*)(Qb + (size_t)(qt * 64 + r) * QKVW + c4);
        *(float4*)(Qs + r * LQ2 + c4) = v;
        *(float4*)(Os + r * LQ2 + c4) = make_float4(0.f, 0.f, 0.f, 0.f);
    }
    if (tid < 64) { rowm[tid] = -1e30f; rowl[tid] = 0.0f; }

    const float scale = 0.08838834764831845f;  // 1/sqrt(128)

    for (int kt = 0; kt <= qt; kt++) {
        const int buf = kt & 1;
        // Prefetch next tile into other buffer (safe: prior iter ended with sync)
        if (kt < qt) {
            const int nb = buf ^ 1;
            const size_t rowoff = (size_t)(kt + 1) * 64;
#pragma unroll
            for (int t = 0; t < 8; t++) {
                int idx = tid + t * 256;
                int r = idx >> 5, c4 = (idx & 31) * 4;
                size_t off = (rowoff + r) * QKVW + c4;
                cpa16(Ks + nb * TILE_F + r * LQ2 + c4, Kb + off);
                cpa16(Vs + nb * TILE_F + r * LQ2 + c4, Vb + off);
            }
            CPA_COMMIT;
            CPA_WAIT(1);
        } else {
            CPA_WAIT(0);
        }
        __syncthreads();

        const float* Kt = Ks + buf * TILE_F;
        const float* Vt = Vs + buf * TILE_F;

        // S = Q K^T  (each warp: 16 rows x 32 cols)
        {
            wmma::fragment<wmma::accumulator, 16, 16, 8, float> sacc[2];
            wmma::fill_fragment(sacc[0], 0.0f);
            wmma::fill_fragment(sacc[1], 0.0f);
#pragma unroll
            for (int kk = 0; kk < 128; kk += 8) {
                wmma::fragment<wmma::matrix_a, 16, 16, 8, wmma::precision::tf32, wmma::row_major> af;
                wmma::load_matrix_sync(af, Qs + wr * 16 * LQ2 + kk, LQ2);
#pragma unroll
                for (int j = 0; j < 2; j++) {
                    wmma::fragment<wmma::matrix_b, 16, 16, 8, wmma::precision::tf32, wmma::col_major> bf;
                    wmma::load_matrix_sync(bf, Kt + (wc * 32 + j * 16) * LQ2 + kk, LQ2);
                    wmma::mma_sync(sacc[j], af, bf, sacc[j]);
                }
            }
            wmma::store_matrix_sync(Ss + wr * 16 * LS2 + wc * 32,      sacc[0], LS2, wmma::mem_row_major);
            wmma::store_matrix_sync(Ss + wr * 16 * LS2 + wc * 32 + 16, sacc[1], LS2, wmma::mem_row_major);
        }
        __syncthreads();

        // Pass 1: scale + mask, partial row max
        {
            int r = tid & 63, part = tid >> 6;
            int sq = qt * 64 + r;
            float pm = -1e30f;
#pragma unroll
            for (int j = 0; j < 16; j++) {
                int col = part * 16 + j;
                int sk = kt * 64 + col;
                float val = Ss[r * LS2 + col] * scale;
                if (sk > sq || mk[sk] == 0) val = -1e30f;
                Ss[r * LS2 + col] = val;
                pm = fmaxf(pm, val);
            }
            red[part * 64 + r] = pm;
        }
        __syncthreads();
        if (tid < 64) {
            float mnew = fmaxf(fmaxf(red[tid], red[64 + tid]),
                               fmaxf(red[128 + tid], red[192 + tid]));
            mnew = fmaxf(mnew, rowm[tid]);
            rowa[tid] = __expf(rowm[tid] - mnew);
            rowm[tid] = mnew;
        }
        __syncthreads();

        // Pass 2: exponentiate (round P), partial sums
        {
            int r = tid & 63, part = tid >> 6;
            float m = rowm[r];
            float psum = 0.0f;
#pragma unroll
            for (int j = 0; j < 16; j++) {
                float p = to_tf32(__expf(Ss[r * LS2 + part * 16 + j] - m));
                Ss[r * LS2 + part * 16 + j] = p;
                psum += p;
            }
            red[part * 64 + r] = psum;
        }
        __syncthreads();
        if (tid < 64)
            rowl[tid] = rowl[tid] * rowa[tid]
                      + red[tid] + red[64 + tid] + red[128 + tid] + red[192 + tid];
        // Rescale O by alpha
        for (int i = tid; i < 64 * 32; i += 256) {
            int r = i >> 5, c4 = (i & 31) * 4;
            float a = rowa[r];
            float4 o4 = *(float4*)(Os + r * LQ2 + c4);
            o4.x *= a; o4.y *= a; o4.z *= a; o4.w *= a;
            *(float4*)(Os + r * LQ2 + c4) = o4;
        }
        __syncthreads();

        // O += P V
        {
            wmma::fragment<wmma::accumulator, 16, 16, 8, float> oacc[4];
#pragma unroll
            for (int j = 0; j < 4; j++)
                wmma::load_matrix_sync(oacc[j], Os + wr * 16 * LQ2 + wc * 64 + j * 16,
                                       LQ2, wmma::mem_row_major);
#pragma unroll
            for (int kk = 0; kk < 64; kk += 8) {
                wmma::fragment<wmma::matrix_a, 16, 16, 8, wmma::precision::tf32, wmma::row_major> af;
                wmma::load_matrix_sync(af, Ss + wr * 16 * LS2 + kk, LS2);
#pragma unroll
                for (int j = 0; j < 4; j++) {
                    wmma::fragment<wmma::matrix_b, 16, 16, 8, wmma::precision::tf32, wmma::row_major> bf;
                    wmma::load_matrix_sync(bf, Vt + kk * LQ2 + wc * 64 + j * 16, LQ2);
                    wmma::mma_sync(oacc[j], af, bf, oacc[j]);
                }
            }
#pragma unroll
            for (int j = 0; j < 4; j++)
                wmma::store_matrix_sync(Os + wr * 16 * LQ2 + wc * 64 + j * 16, oacc[j],
                                        LQ2, wmma::mem_row_major);
        }
        __syncthreads();
    }

    // Epilogue: normalize, sigmoid-gate, tf32-round (feeds Wo GEMM), write
    for (int i = tid; i < 64 * 32; i += 256) {
        int r = i >> 5, c4 = (i & 31) * 4;
        int s = qt * 64 + r;
        float inv = 1.0f / rowl[r];
        float4 g4 = *(const float4*)(Gb + (size_t)s * QKVW + c4);
        float4 o4 = *(float4*)(Os + r * LQ2 + c4);
        float4 res;
        res.x = to_tf32(o4.x * inv * (1.0f / (1.0f + __expf(-g4.x))));
        res.y = to_tf32(o4.y * inv * (1.0f / (1.0f + __expf(-g4.y))));
        res.z = to_tf32(o4.z * inv * (1.0f / (1.0f + __expf(-g4.z))));
        res.w = to_tf32(o4.w * inv * (1.0f / (1.0f + __expf(-g4.w))));
        *(float4*)(aout + ((size_t)b * SEQLEN + s) * HID + h * HD + c4) = res;
    }
}

// ---------------------------------------------------------------------------
extern "C" void kernel_launch(void* const* d_in, const int* in_sizes, int n_in,
                              void* d_out, int out_size)
{
    const float* x     = (const float*)d_in[0];
    const int*   amask = (const int*)  d_in[1];
    const int*   pos   = (const int*)  d_in[2];
    const float* Wq    = (const float*)d_in[3];
    const float* Wk    = (const float*)d_in[4];
    const float* Wv    = (const float*)d_in[5];
    const float* Wo    = (const float*)d_in[6];
    const float* qnw   = (const float*)d_in[7];
    const float* knw   = (const float*)d_in[8];
    float* out = (float*)d_out;

    void *p0, *p1, *p2, *p3, *p4, *p5, *p6;
    cudaGetSymbolAddress(&p0, g_qkv);
    cudaGetSymbolAddress(&p1, g_attn);
    cudaGetSymbolAddress(&p2, g_x);
    cudaGetSymbolAddress(&p3, g_wq);
    cudaGetSymbolAddress(&p4, g_wk);
    cudaGetSymbolAddress(&p5, g_wv);
    cudaGetSymbolAddress(&p6, g_wo);
    float* qkv  = (float*)p0;
    float* attn = (float*)p1;
    float* xr   = (float*)p2;
    float* wq   = (float*)p3;
    float* wk   = (float*)p4;
    float* wv   = (float*)p5;
    float* wo   = (float*)p6;

    // 0) tf32-round inputs once
    round_copy<<<592, 256>>>(x,  xr, T_TOK * HID / 4);
    round_copy<<<592, 256>>>(Wq, wq, HID * 4096 / 4);
    round_copy<<<592, 256>>>(Wk, wk, HID * 1024 / 4);
    round_copy<<<592, 256>>>(Wv, wv, HID * 1024 / 4);
    round_copy<<<592, 256>>>(Wo, wo, HID * HID  / 4);

    // 1) QKV+gate projections into g_qkv [T, 6144]
    gemm_tf32<<<dim3(32, 32), 128>>>(xr, wq, qkv, T_TOK, 4096, HID, HID, 4096, QKVW, 0);
    gemm_tf32<<<dim3(8,  32), 128>>>(xr, wk, qkv, T_TOK, 1024, HID, HID, 1024, QKVW, 4096);
    gemm_tf32<<<dim3(8,  32), 128>>>(xr, wv, qkv, T_TOK, 1024, HID, HID, 1024, QKVW, 5120);

    // 2) QK RMSNorm + RoPE + tf32 rounding of q/k/v (in-place)
    normrope_kernel<<<dim3(T_TOK, 32), 128>>>(qkv, qnw, knw, pos);

    // 3) Tensor-core flash attention + sigmoid gate
    size_t smem_bytes = (size_t)(6 * TILE_F + 64 * LS2 + 256 + 192) * sizeof(float);
    cudaFuncSetAttribute(attn_kernel3, cudaFuncAttributeMaxDynamicSharedMemorySize,
                         (int)smem_bytes);
    attn_kernel3<<<dim3(SEQLEN / 64, NQH, 2), 256, smem_bytes>>>(qkv, amask, attn);

    // 4) Output projection -> d_out
    gemm_tf32<<<dim3(16, 32), 128>>>(attn, wo, out, T_TOK, HID, HID, HID, HID, HID, 0);
}

// round 9
// speedup vs baseline: 1.6885x; 1.2446x over previous
#include <cuda_runtime.h>
#include <cuda_fp16.h>
#include <mma.h>
#include <math.h>

using namespace nvcuda;

// Problem constants
#define T_TOK   4096      // BATCH*SEQ
#define SEQLEN  2048
#define HID     2048
#define NQH     16
#define NKVH    8
#define HD      128
#define QKVW    6144      // 4096 (q+gate) + 1024 (k) + 1024 (v)
#define KDIM    2048

// ---------------------------------------------------------------------------
// Scratch (device globals — no allocation allowed)
// ---------------------------------------------------------------------------
__device__ float  g_qkv[(size_t)T_TOK * QKVW];          // fp32 qkv+gate (GEMM out)
__device__ __half g_xh[(size_t)T_TOK * HID];            // x hi
__device__ __half g_xl[(size_t)T_TOK * HID];            // x lo (residual)
__device__ __half g_bt[(size_t)QKVW * KDIM];            // [Wq|Wk|Wv]^T fp16 [6144][2048]
__device__ __half g_bo[(size_t)HID * KDIM];             // Wo^T fp16 [2048][2048]
__device__ __half g_qh[(size_t)T_TOK * NQH * HD];       // q (norm+rope) fp16
__device__ __half g_kh[(size_t)T_TOK * NKVH * HD];      // k (norm+rope) fp16
__device__ __half g_vh[(size_t)T_TOK * NKVH * HD];      // v fp16
__device__ __half g_ah[(size_t)T_TOK * HID];            // attn out hi
__device__ __half g_al[(size_t)T_TOK * HID];            // attn out lo

__device__ __forceinline__ void cpa16(void* smem_dst, const void* gmem_src) {
    unsigned s = (unsigned)__cvta_generic_to_shared(smem_dst);
    asm volatile("cp.async.cg.shared.global [%0], [%1], 16;" :: "r"(s), "l"(gmem_src));
}
#define CPA_COMMIT asm volatile("cp.async.commit_group;")
#define CPA_WAIT(n) asm volatile("cp.async.wait_group %0;" :: "n"(n))

__device__ __forceinline__ void hsplit(float v, __half& h, __half& l) {
    h = __float2half(v);
    l = __float2half(v - __half2float(h));
}

// ---------------------------------------------------------------------------
// Prep: x fp32 -> half hi/lo
// ---------------------------------------------------------------------------
__global__ __launch_bounds__(256) void split_x(
    const float* __restrict__ in, __half* __restrict__ oh,
    __half* __restrict__ ol, int n)
{
    for (int i = blockIdx.x * blockDim.x + threadIdx.x; i < n; i += gridDim.x * blockDim.x) {
        __half h, l;
        hsplit(in[i], h, l);
        oh[i] = h; ol[i] = l;
    }
}

// Prep: transpose + fp16: W [K=2048][N] fp32 -> out [N][K=2048] half
__global__ __launch_bounds__(256) void tconv(
    const float* __restrict__ W, __half* __restrict__ o, int N)
{
    __shared__ float t[32][33];
    const int n0 = blockIdx.x * 32, k0 = blockIdx.y * 32;
    const int tx = threadIdx.x, ty = threadIdx.y;
#pragma unroll
    for (int j = 0; j < 4; j++)
        t[ty + j * 8][tx] = W[(size_t)(k0 + ty + j * 8) * N + n0 + tx];
    __syncthreads();
#pragma unroll
    for (int j = 0; j < 4; j++)
        o[(size_t)(n0 + ty + j * 8) * KDIM + k0 + tx] = __float2half(t[tx][ty + j * 8]);
}

// ---------------------------------------------------------------------------
// fp16 2-pass GEMM: C[M,N] = (Ah+Al)[M,K] * B^T   (B stored [N][K] fp16)
// CTA 128x128, 128 threads (4 warps, 64x64 each), K-step 32, 3-stage cp.async.
// grid: (N/128, M/128). K = 2048 fixed, lda = ldb = 2048.
// ---------------------------------------------------------------------------
#define GST 30720                 // bytes per stage: Ah 10240 | Al 10240 | B 10240
#define G_AH 0
#define G_AL 10240
#define G_B  20480
#define G_TOTAL (3 * GST)
#define NKSTEP 64                 // 2048 / 32

__global__ __launch_bounds__(128) void gemm_h2(
    const __half* __restrict__ Ah, const __half* __restrict__ Al,
    const __half* __restrict__ B, float* __restrict__ C, int ldc, int cColOff)
{
    extern __shared__ __align__(16) char gsm[];
    const int tid = threadIdx.x;
    const int w   = tid >> 5;
    const int wm  = w & 1;       // 2 row halves of 64
    const int wn  = w >> 1;      // 2 col halves of 64
    const int m0 = blockIdx.y * 128;
    const int n0 = blockIdx.x * 128;

    wmma::fragment<wmma::accumulator, 16, 16, 16, float> acc[4][4];
#pragma unroll
    for (int i = 0; i < 4; i++)
#pragma unroll
        for (int j = 0; j < 4; j++)
            wmma::fill_fragment(acc[i][j], 0.0f);

    // stage loader: 128 rows x 32 halves (4 granules of 16B) for Ah, Al, B
    auto load_stage = [&](int st, int k0) {
        char* s = gsm + st * GST;
#pragma unroll
        for (int t = 0; t < 4; t++) {
            int g = tid + t * 128;          // 0..511
            int r = g >> 2, q = g & 3;
            size_t srcA = (size_t)(m0 + r) * KDIM + k0 + q * 8;
            cpa16(s + G_AH + (r * 40 + q * 8) * 2, Ah + srcA);
            cpa16(s + G_AL + (r * 40 + q * 8) * 2, Al + srcA);
            size_t srcB = (size_t)(n0 + r) * KDIM + k0 + q * 8;
            cpa16(s + G_B  + (r * 40 + q * 8) * 2, B + srcB);
        }
        CPA_COMMIT;
    };

    load_stage(0, 0);
    load_stage(1, 32);

    for (int kt = 0; kt < NKSTEP; kt++) {
        if (kt == NKSTEP - 1) { CPA_WAIT(0); } else { CPA_WAIT(1); }
        __syncthreads();
        if (kt + 2 < NKSTEP) load_stage((kt + 2) % 3, (kt + 2) * 32);

        const __half* sAh = (const __half*)(gsm + (kt % 3) * GST + G_AH);
        const __half* sAl = (const __half*)(gsm + (kt % 3) * GST + G_AL);
        const __half* sB  = (const __half*)(gsm + (kt % 3) * GST + G_B);

#pragma unroll
        for (int kk = 0; kk < 32; kk += 16) {
            wmma::fragment<wmma::matrix_a, 16, 16, 16, __half, wmma::row_major> ahf[4], alf[4];
            wmma::fragment<wmma::matrix_b, 16, 16, 16, __half, wmma::col_major> bf[4];
#pragma unroll
            for (int i = 0; i < 4; i++) {
                wmma::load_matrix_sync(ahf[i], sAh + (wm * 64 + i * 16) * 40 + kk, 40);
                wmma::load_matrix_sync(alf[i], sAl + (wm * 64 + i * 16) * 40 + kk, 40);
            }
#pragma unroll
            for (int j = 0; j < 4; j++)
                wmma::load_matrix_sync(bf[j], sB + (wn * 64 + j * 16) * 40 + kk, 40);
#pragma unroll
            for (int i = 0; i < 4; i++)
#pragma unroll
                for (int j = 0; j < 4; j++) {
                    wmma::mma_sync(acc[i][j], ahf[i], bf[j], acc[i][j]);
                    wmma::mma_sync(acc[i][j], alf[i], bf[j], acc[i][j]);
                }
        }
    }

#pragma unroll
    for (int i = 0; i < 4; i++)
#pragma unroll
        for (int j = 0; j < 4; j++)
            wmma::store_matrix_sync(
                C + (size_t)(m0 + wm * 64 + i * 16) * ldc + cColOff + n0 + wn * 64 + j * 16,
                acc[i][j], ldc, wmma::mem_row_major);
}

// ---------------------------------------------------------------------------
// RMSNorm + partial RoPE; emits q/k/v as fp16 arrays. Gate stays in g_qkv.
// grid: (4096, 32): hh 0..15 q, 16..23 k, 24..31 v
// ---------------------------------------------------------------------------
__global__ __launch_bounds__(128) void normrope_kernel(
    const float* __restrict__ qkv,
    __half* __restrict__ qh, __half* __restrict__ kh, __half* __restrict__ vh,
    const float* __restrict__ qnw, const float* __restrict__ knw,
    const int* __restrict__ positions)
{
    const int t  = blockIdx.x;
    const int hh = blockIdx.y;
    const int d  = threadIdx.x;

    if (hh >= NQH + NKVH) {  // v heads: convert only
        int kvh = hh - NQH - NKVH;
        float v = qkv[(size_t)t * QKVW + 5120 + kvh * HD + d];
        vh[((size_t)t * NKVH + kvh) * HD + d] = __float2half(v);
        return;
    }

    const float* vec;
    const float* w;
    __half* outp;
    if (hh < NQH) {
        vec = qkv + (size_t)t * QKVW + hh * 256;
        w = qnw;
        outp = qh + ((size_t)t * NQH + hh) * HD;
    } else {
        int kvh = hh - NQH;
        vec = qkv + (size_t)t * QKVW + 4096 + kvh * HD;
        w = knw;
        outp = kh + ((size_t)t * NKVH + kvh) * HD;
    }

    float x = vec[d];

    __shared__ float sred[4];
    __shared__ float sv[128];
    int lane = d & 31, wrp = d >> 5;
    float ss = x * x;
#pragma unroll
    for (int o = 16; o > 0; o >>= 1) ss += __shfl_xor_sync(0xffffffffu, ss, o);
    if (lane == 0) sred[wrp] = ss;
    __syncthreads();
    float tot = sred[0] + sred[1] + sred[2] + sred[3];
    float r = rsqrtf(tot * (1.0f / 128.0f) + 1e-6f);
    float y = x * r * (1.0f + w[d]);

    sv[d] = y;
    __syncthreads();

    float out = y;
    if (d < 32) {
        int j = d & 15;
        float inv = powf(10000000.0f, -(float)j * (1.0f / 16.0f));
        float ang = (float)positions[t] * inv;
        float c = cosf(ang), s = sinf(ang);
        int base = (d < 16) ? d : (d - 16);
        float x1 = sv[base];
        float x2 = sv[base + 16];
        out = (d < 16) ? (x1 * c - x2 * s) : (x1 * s + x2 * c);
    }
    outp[d] = __float2half(out);
}

// ---------------------------------------------------------------------------
// fp16 tensor-core flash attention, cp.async double-buffered K/V.
// BQ=BK=64, 256 threads, 8 warps. Q/K/V/P fp16; S/O fp32.
// grid: (32 qtiles [reversed], 16 heads, 2 batch)
// Epilogue: sigmoid gate (fp32 from g_qkv), writes half hi/lo for Wo GEMM.
// ---------------------------------------------------------------------------
#define AQ_LD 136     // half stride for Q/K/V tiles (128 + 8)
#define AS_LD 68      // float stride for S tile
#define AP_LD 72      // half stride for P tile
#define AO_LD 132     // float stride for O tile
// smem byte offsets
#define OFF_Q   0
#define OFF_K0  17408
#define OFF_K1  34816
#define OFF_V0  52224
#define OFF_V1  69632
#define OFF_P   87040
#define OFF_S   96256
#define OFF_O   113664
#define OFF_RED 147456
#define OFF_RM  148480
#define OFF_RL  148736
#define OFF_RA  148992
#define ATT_SMEM 149248

__global__ __launch_bounds__(256) void attn_h(
    const __half* __restrict__ qh, const __half* __restrict__ kh,
    const __half* __restrict__ vh, const float* __restrict__ qkv,
    const int* __restrict__ amask,
    __half* __restrict__ aoh, __half* __restrict__ aol)
{
    extern __shared__ __align__(16) char asm_[];
    __half* Qs  = (__half*)(asm_ + OFF_Q);
    __half* Ks0 = (__half*)(asm_ + OFF_K0);
    __half* Ks1 = (__half*)(asm_ + OFF_K1);
    __half* Vs0 = (__half*)(asm_ + OFF_V0);
    __half* Vs1 = (__half*)(asm_ + OFF_V1);
    __half* Ps  = (__half*)(asm_ + OFF_P);
    float*  Ss  = (float*)(asm_ + OFF_S);
    float*  Os  = (float*)(asm_ + OFF_O);
    float*  red = (float*)(asm_ + OFF_RED);
    float*  rowm = (float*)(asm_ + OFF_RM);
    float*  rowl = (float*)(asm_ + OFF_RL);
    float*  rowa = (float*)(asm_ + OFF_RA);

    const int qt = (int)gridDim.x - 1 - (int)blockIdx.x;
    const int h  = blockIdx.y;
    const int b  = blockIdx.z;
    const int kvh = h >> 1;

    // row strides (halves): q rows 2048 apart, k/v rows 1024 apart
    const __half* Qb = qh + ((size_t)b * SEQLEN * NQH + h) * HD;
    const __half* Kb = kh + ((size_t)b * SEQLEN * NKVH + kvh) * HD;
    const __half* Vb = vh + ((size_t)b * SEQLEN * NKVH + kvh) * HD;
    const float*  Gb = qkv + (size_t)b * SEQLEN * QKVW + h * 256 + 128;
    const int*    mk = amask + b * SEQLEN;

    const int tid = threadIdx.x;
    const int w   = tid >> 5;
    const int wr  = w & 3;      // 4 row groups of 16
    const int wc  = w >> 2;     // 2 col halves

    // Prefetch K/V tile 0 (64 rows x 16 granules each)
#pragma unroll
    for (int t = 0; t < 4; t++) {
        int g = tid + t * 256;
        int r = g >> 4, q = g & 15;
        cpa16(Ks0 + r * AQ_LD + q * 8, Kb + (size_t)r * (NKVH * HD) + q * 8);
        cpa16(Vs0 + r * AQ_LD + q * 8, Vb + (size_t)r * (NKVH * HD) + q * 8);
    }
    CPA_COMMIT;

    // Load Q tile + zero O
#pragma unroll
    for (int t = 0; t < 4; t++) {
        int g = tid + t * 256;
        int r = g >> 4, q = g & 15;
        cpa16(Qs + r * AQ_LD + q * 8, Qb + (size_t)(qt * 64 + r) * (NQH * HD) + q * 8);
    }
    CPA_COMMIT;
    for (int i = tid; i < 64 * 32; i += 256) {
        int r = i >> 5, c4 = (i & 31) * 4;
        *(float4*)(Os + r * AO_LD + c4) = make_float4(0.f, 0.f, 0.f, 0.f);
    }
    if (tid < 64) { rowm[tid] = -1e30f; rowl[tid] = 0.0f; }

    const float scale = 0.08838834764831845f;  // 1/sqrt(128)

    for (int kt = 0; kt <= qt; kt++) {
        const int buf = kt & 1;
        if (kt < qt) {
            __half* Kn = (buf ^ 1) ? Ks1 : Ks0;
            __half* Vn = (buf ^ 1) ? Vs1 : Vs0;
            const size_t row0 = (size_t)(kt + 1) * 64;
#pragma unroll
            for (int t = 0; t < 4; t++) {
                int g = tid + t * 256;
                int r = g >> 4, q = g & 15;
                cpa16(Kn + r * AQ_LD + q * 8, Kb + (row0 + r) * (NKVH * HD) + q * 8);
                cpa16(Vn + r * AQ_LD + q * 8, Vb + (row0 + r) * (NKVH * HD) + q * 8);
            }
            CPA_COMMIT;
            CPA_WAIT(1);
        } else {
            CPA_WAIT(0);
        }
        __syncthreads();

        const __half* Kt = buf ? Ks1 : Ks0;
        const __half* Vt = buf ? Vs1 : Vs0;

        // S = Q K^T  (each warp 16 rows x 32 cols; kk over 128 by 16)
        {
            wmma::fragment<wmma::accumulator, 16, 16, 16, float> sacc[2];
            wmma::fill_fragment(sacc[0], 0.0f);
            wmma::fill_fragment(sacc[1], 0.0f);
#pragma unroll
            for (int kk = 0; kk < 128; kk += 16) {
                wmma::fragment<wmma::matrix_a, 16, 16, 16, __half, wmma::row_major> af;
                wmma::load_matrix_sync(af, Qs + wr * 16 * AQ_LD + kk, AQ_LD);
#pragma unroll
                for (int j = 0; j < 2; j++) {
                    wmma::fragment<wmma::matrix_b, 16, 16, 16, __half, wmma::col_major> bf;
                    wmma::load_matrix_sync(bf, Kt + (wc * 32 + j * 16) * AQ_LD + kk, AQ_LD);
                    wmma::mma_sync(sacc[j], af, bf, sacc[j]);
                }
            }
            wmma::store_matrix_sync(Ss + wr * 16 * AS_LD + wc * 32,      sacc[0], AS_LD, wmma::mem_row_major);
            wmma::store_matrix_sync(Ss + wr * 16 * AS_LD + wc * 32 + 16, sacc[1], AS_LD, wmma::mem_row_major);
        }
        __syncthreads();

        // Pass 1: scale + mask + partial row max
        {
            int r = tid & 63, part = tid >> 6;
            int sq = qt * 64 + r;
            float pm = -1e30f;
#pragma unroll
            for (int j = 0; j < 16; j++) {
                int col = part * 16 + j;
                int sk = kt * 64 + col;
                float val = Ss[r * AS_LD + col] * scale;
                if (sk > sq || mk[sk] == 0) val = -1e30f;
                Ss[r * AS_LD + col] = val;
                pm = fmaxf(pm, val);
            }
            red[part * 64 + r] = pm;
        }
        __syncthreads();
        if (tid < 64) {
            float mnew = fmaxf(fmaxf(red[tid], red[64 + tid]),
                               fmaxf(red[128 + tid], red[192 + tid]));
            mnew = fmaxf(mnew, rowm[tid]);
            rowa[tid] = __expf(rowm[tid] - mnew);
            rowm[tid] = mnew;
        }
        __syncthreads();

        // Pass 2: exponentiate -> P (fp16), partial sums
        {
            int r = tid & 63, part = tid >> 6;
            float m = rowm[r];
            float psum = 0.0f;
#pragma unroll
            for (int j = 0; j < 16; j++) {
                int col = part * 16 + j;
                __half ph = __float2half(__expf(Ss[r * AS_LD + col] - m));
                Ps[r * AP_LD + col] = ph;
                psum += __half2float(ph);
            }
            red[part * 64 + r] = psum;
        }
        __syncthreads();
        if (tid < 64)
            rowl[tid] = rowl[tid] * rowa[tid]
                      + red[tid] + red[64 + tid] + red[128 + tid] + red[192 + tid];
        // Rescale O by alpha
        for (int i = tid; i < 64 * 32; i += 256) {
            int r = i >> 5, c4 = (i & 31) * 4;
            float a = rowa[r];
            float4 o4 = *(float4*)(Os + r * AO_LD + c4);
            o4.x *= a; o4.y *= a; o4.z *= a; o4.w *= a;
            *(float4*)(Os + r * AO_LD + c4) = o4;
        }
        __syncthreads();

        // O += P V  (each warp 16 rows x 64 d-cols; kk over 64 keys by 16)
        {
            wmma::fragment<wmma::accumulator, 16, 16, 16, float> oacc[4];
#pragma unroll
            for (int j = 0; j < 4; j++)
                wmma::load_matrix_sync(oacc[j], Os + wr * 16 * AO_LD + wc * 64 + j * 16,
                                       AO_LD, wmma::mem_row_major);
#pragma unroll
            for (int kk = 0; kk < 64; kk += 16) {
                wmma::fragment<wmma::matrix_a, 16, 16, 16, __half, wmma::row_major> af;
                wmma::load_matrix_sync(af, Ps + wr * 16 * AP_LD + kk, AP_LD);
#pragma unroll
                for (int j = 0; j < 4; j++) {
                    wmma::fragment<wmma::matrix_b, 16, 16, 16, __half, wmma::row_major> bf;
                    wmma::load_matrix_sync(bf, Vt + kk * AQ_LD + wc * 64 + j * 16, AQ_LD);
                    wmma::mma_sync(oacc[j], af, bf, oacc[j]);
                }
            }
#pragma unroll
            for (int j = 0; j < 4; j++)
                wmma::store_matrix_sync(Os + wr * 16 * AO_LD + wc * 64 + j * 16, oacc[j],
                                        AO_LD, wmma::mem_row_major);
        }
        __syncthreads();
    }

    // Epilogue: normalize, sigmoid-gate, split to half hi/lo
    for (int i = tid; i < 64 * 32; i += 256) {
        int r = i >> 5, c4 = (i & 31) * 4;
        int s = qt * 64 + r;
        float inv = 1.0f / rowl[r];
        float4 g4 = *(const float4*)(Gb + (size_t)s * QKVW + c4);
        float4 o4 = *(float4*)(Os + r * AO_LD + c4);
        float res[4];
        res[0] = o4.x * inv * (1.0f / (1.0f + __expf(-g4.x)));
        res[1] = o4.y * inv * (1.0f / (1.0f + __expf(-g4.y)));
        res[2] = o4.z * inv * (1.0f / (1.0f + __expf(-g4.z)));
        res[3] = o4.w * inv * (1.0f / (1.0f + __expf(-g4.w)));
        size_t idx = ((size_t)b * SEQLEN + s) * HID + h * HD + c4;
#pragma unroll
        for (int j = 0; j < 4; j++) {
            __half hh, ll;
            hsplit(res[j], hh, ll);
            aoh[idx + j] = hh; aol[idx + j] = ll;
        }
    }
}

// ---------------------------------------------------------------------------
extern "C" void kernel_launch(void* const* d_in, const int* in_sizes, int n_in,
                              void* d_out, int out_size)
{
    const float* x     = (const float*)d_in[0];
    const int*   amask = (const int*)  d_in[1];
    const int*   pos   = (const int*)  d_in[2];
    const float* Wq    = (const float*)d_in[3];
    const float* Wk    = (const float*)d_in[4];
    const float* Wv    = (const float*)d_in[5];
    const float* Wo    = (const float*)d_in[6];
    const float* qnw   = (const float*)d_in[7];
    const float* knw   = (const float*)d_in[8];
    float* out = (float*)d_out;

    void *p_qkv, *p_xh, *p_xl, *p_bt, *p_bo, *p_qh, *p_kh, *p_vh, *p_ah, *p_al;
    cudaGetSymbolAddress(&p_qkv, g_qkv);
    cudaGetSymbolAddress(&p_xh,  g_xh);
    cudaGetSymbolAddress(&p_xl,  g_xl);
    cudaGetSymbolAddress(&p_bt,  g_bt);
    cudaGetSymbolAddress(&p_bo,  g_bo);
    cudaGetSymbolAddress(&p_qh,  g_qh);
    cudaGetSymbolAddress(&p_kh,  g_kh);
    cudaGetSymbolAddress(&p_vh,  g_vh);
    cudaGetSymbolAddress(&p_ah,  g_ah);
    cudaGetSymbolAddress(&p_al,  g_al);
    float*  qkv = (float*)p_qkv;
    __half* xh  = (__half*)p_xh;
    __half* xl  = (__half*)p_xl;
    __half* bt  = (__half*)p_bt;
    __half* bo  = (__half*)p_bo;
    __half* qh  = (__half*)p_qh;
    __half* kh  = (__half*)p_kh;
    __half* vh  = (__half*)p_vh;
    __half* ah  = (__half*)p_ah;
    __half* al  = (__half*)p_al;

    // 0) Prep: split x; transpose+convert weights
    split_x<<<1184, 256>>>(x, xh, xl, T_TOK * HID);
    tconv<<<dim3(4096 / 32, KDIM / 32), dim3(32, 8)>>>(Wq, bt, 4096);
    tconv<<<dim3(1024 / 32, KDIM / 32), dim3(32, 8)>>>(Wk, bt + (size_t)4096 * KDIM, 1024);
    tconv<<<dim3(1024 / 32, KDIM / 32), dim3(32, 8)>>>(Wv, bt + (size_t)5120 * KDIM, 1024);
    tconv<<<dim3(2048 / 32, KDIM / 32), dim3(32, 8)>>>(Wo, bo, 2048);

    // 1) QKV+gate projection -> g_qkv fp32 [4096][6144]
    cudaFuncSetAttribute(gemm_h2, cudaFuncAttributeMaxDynamicSharedMemorySize, G_TOTAL);
    gemm_h2<<<dim3(48, 32), 128, G_TOTAL>>>(xh, xl, bt, qkv, QKVW, 0);

    // 2) RMSNorm + RoPE -> fp16 q/k/v
    normrope_kernel<<<dim3(T_TOK, 32), 128>>>(qkv, qh, kh, vh, qnw, knw, pos);

    // 3) fp16 flash attention + sigmoid gate -> half hi/lo
    cudaFuncSetAttribute(attn_h, cudaFuncAttributeMaxDynamicSharedMemorySize, ATT_SMEM);
    attn_h<<<dim3(SEQLEN / 64, NQH, 2), 256, ATT_SMEM>>>(qh, kh, vh, qkv, amask, ah, al);

    // 4) Output projection -> d_out fp32
    gemm_h2<<<dim3(16, 32), 128, G_TOTAL>>>(ah, al, bo, out, HID, 0);
}

// round 10
// speedup vs baseline: 3.4503x; 2.0435x over previous
#include <cuda_runtime.h>
#include <cuda_fp16.h>
#include <mma.h>
#include <math.h>

using namespace nvcuda;

// Problem constants
#define T_TOK   4096      // BATCH*SEQ
#define SEQLEN  2048
#define HID     2048
#define NQH     16
#define NKVH    8
#define HD      128
#define QKVW    6144      // 4096 (q+gate) + 1024 (k) + 1024 (v)
#define KDIM    2048

// ---------------------------------------------------------------------------
// Scratch (device globals — no allocation allowed)
// ---------------------------------------------------------------------------
__device__ float  g_qkv[(size_t)T_TOK * QKVW];          // fp32 qkv+gate (GEMM out)
__device__ __half g_xh[(size_t)T_TOK * HID];            // x fp16
__device__ __half g_bt[(size_t)QKVW * KDIM];            // [Wq|Wk|Wv]^T fp16 [6144][2048]
__device__ __half g_bo[(size_t)HID * KDIM];             // Wo^T fp16 [2048][2048]
__device__ __half g_qh[(size_t)T_TOK * NQH * HD];       // q (norm+rope) fp16
__device__ __half g_kh[(size_t)T_TOK * NKVH * HD];      // k (norm+rope) fp16
__device__ __half g_vh[(size_t)T_TOK * NKVH * HD];      // v fp16
__device__ __half g_ah[(size_t)T_TOK * HID];            // attn out fp16

__device__ __forceinline__ void cpa16(void* smem_dst, const void* gmem_src) {
    unsigned s = (unsigned)__cvta_generic_to_shared(smem_dst);
    asm volatile("cp.async.cg.shared.global [%0], [%1], 16;" :: "r"(s), "l"(gmem_src));
}
#define CPA_COMMIT asm volatile("cp.async.commit_group;")
#define CPA_WAIT(n) asm volatile("cp.async.wait_group %0;" :: "n"(n))

// ---------------------------------------------------------------------------
// Prep: x fp32 -> fp16 (layout already [T][K], K contiguous)
// ---------------------------------------------------------------------------
__global__ __launch_bounds__(256) void conv_x(
    const float* __restrict__ in, __half* __restrict__ o, int n)
{
    for (int i = blockIdx.x * blockDim.x + threadIdx.x; i < n; i += gridDim.x * blockDim.x)
        o[i] = __float2half(in[i]);
}

// Prep: transpose + fp16: W [K=2048][N] fp32 -> out [N][K=2048] half
__global__ __launch_bounds__(256) void tconv(
    const float* __restrict__ W, __half* __restrict__ o, int N)
{
    __shared__ float t[32][33];
    const int n0 = blockIdx.x * 32, k0 = blockIdx.y * 32;
    const int tx = threadIdx.x, ty = threadIdx.y;
#pragma unroll
    for (int j = 0; j < 4; j++)
        t[ty + j * 8][tx] = W[(size_t)(k0 + ty + j * 8) * N + n0 + tx];
    __syncthreads();
#pragma unroll
    for (int j = 0; j < 4; j++)
        o[(size_t)(n0 + ty + j * 8) * KDIM + k0 + tx] = __float2half(t[tx][ty + j * 8]);
}

// ---------------------------------------------------------------------------
// fp16 single-pass GEMM: C[M,N] = A[M,K] * B^T   (B stored [N][K] fp16)
// CTA 128x128, 128 threads (4 warps, 64x64 each), K-step 32, 3-stage cp.async.
// grid: (N/128, M/128). K = 2048 fixed.
// ---------------------------------------------------------------------------
#define GST 20480                 // bytes per stage: A 10240 | B 10240
#define G_A 0
#define G_B 10240
#define G_TOTAL (3 * GST)
#define NKSTEP 64                 // 2048 / 32

__global__ __launch_bounds__(128) void gemm_h1(
    const __half* __restrict__ A, const __half* __restrict__ B,
    float* __restrict__ C, int ldc)
{
    extern __shared__ __align__(16) char gsm[];
    const int tid = threadIdx.x;
    const int w   = tid >> 5;
    const int wm  = w & 1;       // 2 row halves of 64
    const int wn  = w >> 1;      // 2 col halves of 64
    const int m0 = blockIdx.y * 128;
    const int n0 = blockIdx.x * 128;

    wmma::fragment<wmma::accumulator, 16, 16, 16, float> acc[4][4];
#pragma unroll
    for (int i = 0; i < 4; i++)
#pragma unroll
        for (int j = 0; j < 4; j++)
            wmma::fill_fragment(acc[i][j], 0.0f);

    // stage loader: 128 rows x 32 halves (4 granules of 16B) for A and B
    auto load_stage = [&](int st, int k0) {
        char* s = gsm + st * GST;
#pragma unroll
        for (int t = 0; t < 4; t++) {
            int g = tid + t * 128;          // 0..511
            int r = g >> 2, q = g & 3;
            cpa16(s + G_A + (r * 40 + q * 8) * 2, A + (size_t)(m0 + r) * KDIM + k0 + q * 8);
            cpa16(s + G_B + (r * 40 + q * 8) * 2, B + (size_t)(n0 + r) * KDIM + k0 + q * 8);
        }
        CPA_COMMIT;
    };

    load_stage(0, 0);
    load_stage(1, 32);

    for (int kt = 0; kt < NKSTEP; kt++) {
        if (kt == NKSTEP - 1) { CPA_WAIT(0); } else { CPA_WAIT(1); }
        __syncthreads();
        if (kt + 2 < NKSTEP) load_stage((kt + 2) % 3, (kt + 2) * 32);

        const __half* sA = (const __half*)(gsm + (kt % 3) * GST + G_A);
        const __half* sB = (const __half*)(gsm + (kt % 3) * GST + G_B);

#pragma unroll
        for (int kk = 0; kk < 32; kk += 16) {
            wmma::fragment<wmma::matrix_a, 16, 16, 16, __half, wmma::row_major> af[4];
            wmma::fragment<wmma::matrix_b, 16, 16, 16, __half, wmma::col_major> bf[4];
#pragma unroll
            for (int i = 0; i < 4; i++)
                wmma::load_matrix_sync(af[i], sA + (wm * 64 + i * 16) * 40 + kk, 40);
#pragma unroll
            for (int j = 0; j < 4; j++)
                wmma::load_matrix_sync(bf[j], sB + (wn * 64 + j * 16) * 40 + kk, 40);
#pragma unroll
            for (int i = 0; i < 4; i++)
#pragma unroll
                for (int j = 0; j < 4; j++)
                    wmma::mma_sync(acc[i][j], af[i], bf[j], acc[i][j]);
        }
    }

#pragma unroll
    for (int i = 0; i < 4; i++)
#pragma unroll
        for (int j = 0; j < 4; j++)
            wmma::store_matrix_sync(
                C + (size_t)(m0 + wm * 64 + i * 16) * ldc + n0 + wn * 64 + j * 16,
                acc[i][j], ldc, wmma::mem_row_major);
}

// ---------------------------------------------------------------------------
// RMSNorm + partial RoPE; emits q/k/v as fp16 arrays. Gate stays in g_qkv.
// grid: (4096, 32): hh 0..15 q, 16..23 k, 24..31 v
// ---------------------------------------------------------------------------
__global__ __launch_bounds__(128) void normrope_kernel(
    const float* __restrict__ qkv,
    __half* __restrict__ qh, __half* __restrict__ kh, __half* __restrict__ vh,
    const float* __restrict__ qnw, const float* __restrict__ knw,
    const int* __restrict__ positions)
{
    const int t  = blockIdx.x;
    const int hh = blockIdx.y;
    const int d  = threadIdx.x;

    if (hh >= NQH + NKVH) {  // v heads: convert only
        int kvh = hh - NQH - NKVH;
        float v = qkv[(size_t)t * QKVW + 5120 + kvh * HD + d];
        vh[((size_t)t * NKVH + kvh) * HD + d] = __float2half(v);
        return;
    }

    const float* vec;
    const float* w;
    __half* outp;
    if (hh < NQH) {
        vec = qkv + (size_t)t * QKVW + hh * 256;
        w = qnw;
        outp = qh + ((size_t)t * NQH + hh) * HD;
    } else {
        int kvh = hh - NQH;
        vec = qkv + (size_t)t * QKVW + 4096 + kvh * HD;
        w = knw;
        outp = kh + ((size_t)t * NKVH + kvh) * HD;
    }

    float x = vec[d];

    __shared__ float sred[4];
    __shared__ float sv[128];
    int lane = d & 31, wrp = d >> 5;
    float ss = x * x;
#pragma unroll
    for (int o = 16; o > 0; o >>= 1) ss += __shfl_xor_sync(0xffffffffu, ss, o);
    if (lane == 0) sred[wrp] = ss;
    __syncthreads();
    float tot = sred[0] + sred[1] + sred[2] + sred[3];
    float r = rsqrtf(tot * (1.0f / 128.0f) + 1e-6f);
    float y = x * r * (1.0f + w[d]);

    sv[d] = y;
    __syncthreads();

    float out = y;
    if (d < 32) {
        int j = d & 15;
        float inv = powf(10000000.0f, -(float)j * (1.0f / 16.0f));
        float ang = (float)positions[t] * inv;
        float c = cosf(ang), s = sinf(ang);
        int base = (d < 16) ? d : (d - 16);
        float x1 = sv[base];
        float x2 = sv[base + 16];
        out = (d < 16) ? (x1 * c - x2 * s) : (x1 * s + x2 * c);
    }
    outp[d] = __float2half(out);
}

// ---------------------------------------------------------------------------
// fp16 tensor-core flash attention, cp.async double-buffered K/V.
// BQ=BK=64, 256 threads, 8 warps. Q/K/V/P fp16; S/O fp32.
// grid: (32 qtiles [reversed], 16 heads, 2 batch)
// Epilogue: sigmoid gate (fp32 from g_qkv), writes fp16 for Wo GEMM.
// ---------------------------------------------------------------------------
#define AQ_LD 136     // half stride for Q/K/V tiles (128 + 8)
#define AS_LD 68      // float stride for S tile
#define AP_LD 72      // half stride for P tile
#define AO_LD 132     // float stride for O tile
// smem byte offsets
#define OFF_Q   0
#define OFF_K0  17408
#define OFF_K1  34816
#define OFF_V0  52224
#define OFF_V1  69632
#define OFF_P   87040
#define OFF_S   96256
#define OFF_O   113664
#define OFF_RED 147456
#define OFF_RM  148480
#define OFF_RL  148736
#define OFF_RA  148992
#define ATT_SMEM 149248

__global__ __launch_bounds__(256) void attn_h(
    const __half* __restrict__ qh, const __half* __restrict__ kh,
    const __half* __restrict__ vh, const float* __restrict__ qkv,
    const int* __restrict__ amask,
    __half* __restrict__ ao)
{
    extern __shared__ __align__(16) char asm_[];
    __half* Qs  = (__half*)(asm_ + OFF_Q);
    __half* Ks0 = (__half*)(asm_ + OFF_K0);
    __half* Ks1 = (__half*)(asm_ + OFF_K1);
    __half* Vs0 = (__half*)(asm_ + OFF_V0);
    __half* Vs1 = (__half*)(asm_ + OFF_V1);
    __half* Ps  = (__half*)(asm_ + OFF_P);
    float*  Ss  = (float*)(asm_ + OFF_S);
    float*  Os  = (float*)(asm_ + OFF_O);
    float*  red = (float*)(asm_ + OFF_RED);
    float*  rowm = (float*)(asm_ + OFF_RM);
    float*  rowl = (float*)(asm_ + OFF_RL);
    float*  rowa = (float*)(asm_ + OFF_RA);

    const int qt = (int)gridDim.x - 1 - (int)blockIdx.x;
    const int h  = blockIdx.y;
    const int b  = blockIdx.z;
    const int kvh = h >> 1;

    const __half* Qb = qh + ((size_t)b * SEQLEN * NQH + h) * HD;
    const __half* Kb = kh + ((size_t)b * SEQLEN * NKVH + kvh) * HD;
    const __half* Vb = vh + ((size_t)b * SEQLEN * NKVH + kvh) * HD;
    const float*  Gb = qkv + (size_t)b * SEQLEN * QKVW + h * 256 + 128;
    const int*    mk = amask + b * SEQLEN;

    const int tid = threadIdx.x;
    const int w   = tid >> 5;
    const int wr  = w & 3;      // 4 row groups of 16
    const int wc  = w >> 2;     // 2 col halves

    // Prefetch K/V tile 0
#pragma unroll
    for (int t = 0; t < 4; t++) {
        int g = tid + t * 256;
        int r = g >> 4, q = g & 15;
        cpa16(Ks0 + r * AQ_LD + q * 8, Kb + (size_t)r * (NKVH * HD) + q * 8);
        cpa16(Vs0 + r * AQ_LD + q * 8, Vb + (size_t)r * (NKVH * HD) + q * 8);
    }
    CPA_COMMIT;

    // Load Q tile + zero O
#pragma unroll
    for (int t = 0; t < 4; t++) {
        int g = tid + t * 256;
        int r = g >> 4, q = g & 15;
        cpa16(Qs + r * AQ_LD + q * 8, Qb + (size_t)(qt * 64 + r) * (NQH * HD) + q * 8);
    }
    CPA_COMMIT;
    for (int i = tid; i < 64 * 32; i += 256) {
        int r = i >> 5, c4 = (i & 31) * 4;
        *(float4*)(Os + r * AO_LD + c4) = make_float4(0.f, 0.f, 0.f, 0.f);
    }
    if (tid < 64) { rowm[tid] = -1e30f; rowl[tid] = 0.0f; }

    const float scale = 0.08838834764831845f;  // 1/sqrt(128)

    for (int kt = 0; kt <= qt; kt++) {
        const int buf = kt & 1;
        if (kt < qt) {
            __half* Kn = (buf ^ 1) ? Ks1 : Ks0;
            __half* Vn = (buf ^ 1) ? Vs1 : Vs0;
            const size_t row0 = (size_t)(kt + 1) * 64;
#pragma unroll
            for (int t = 0; t < 4; t++) {
                int g = tid + t * 256;
                int r = g >> 4, q = g & 15;
                cpa16(Kn + r * AQ_LD + q * 8, Kb + (row0 + r) * (NKVH * HD) + q * 8);
                cpa16(Vn + r * AQ_LD + q * 8, Vb + (row0 + r) * (NKVH * HD) + q * 8);
            }
            CPA_COMMIT;
            CPA_WAIT(1);
        } else {
            CPA_WAIT(0);
        }
        __syncthreads();

        const __half* Kt = buf ? Ks1 : Ks0;
        const __half* Vt = buf ? Vs1 : Vs0;

        // S = Q K^T
        {
            wmma::fragment<wmma::accumulator, 16, 16, 16, float> sacc[2];
            wmma::fill_fragment(sacc[0], 0.0f);
            wmma::fill_fragment(sacc[1], 0.0f);
#pragma unroll
            for (int kk = 0; kk < 128; kk += 16) {
                wmma::fragment<wmma::matrix_a, 16, 16, 16, __half, wmma::row_major> af;
                wmma::load_matrix_sync(af, Qs + wr * 16 * AQ_LD + kk, AQ_LD);
#pragma unroll
                for (int j = 0; j < 2; j++) {
                    wmma::fragment<wmma::matrix_b, 16, 16, 16, __half, wmma::col_major> bf;
                    wmma::load_matrix_sync(bf, Kt + (wc * 32 + j * 16) * AQ_LD + kk, AQ_LD);
                    wmma::mma_sync(sacc[j], af, bf, sacc[j]);
                }
            }
            wmma::store_matrix_sync(Ss + wr * 16 * AS_LD + wc * 32,      sacc[0], AS_LD, wmma::mem_row_major);
            wmma::store_matrix_sync(Ss + wr * 16 * AS_LD + wc * 32 + 16, sacc[1], AS_LD, wmma::mem_row_major);
        }
        __syncthreads();

        // Pass 1: scale + mask + partial row max
        {
            int r = tid & 63, part = tid >> 6;
            int sq = qt * 64 + r;
            float pm = -1e30f;
#pragma unroll
            for (int j = 0; j < 16; j++) {
                int col = part * 16 + j;
                int sk = kt * 64 + col;
                float val = Ss[r * AS_LD + col] * scale;
                if (sk > sq || mk[sk] == 0) val = -1e30f;
                Ss[r * AS_LD + col] = val;
                pm = fmaxf(pm, val);
            }
            red[part * 64 + r] = pm;
        }
        __syncthreads();
        if (tid < 64) {
            float mnew = fmaxf(fmaxf(red[tid], red[64 + tid]),
                               fmaxf(red[128 + tid], red[192 + tid]));
            mnew = fmaxf(mnew, rowm[tid]);
            rowa[tid] = __expf(rowm[tid] - mnew);
            rowm[tid] = mnew;
        }
        __syncthreads();

        // Pass 2: exponentiate -> P (fp16), partial sums
        {
            int r = tid & 63, part = tid >> 6;
            float m = rowm[r];
            float psum = 0.0f;
#pragma unroll
            for (int j = 0; j < 16; j++) {
                int col = part * 16 + j;
                __half ph = __float2half(__expf(Ss[r * AS_LD + col] - m));
                Ps[r * AP_LD + col] = ph;
                psum += __half2float(ph);
            }
            red[part * 64 + r] = psum;
        }
        __syncthreads();
        if (tid < 64)
            rowl[tid] = rowl[tid] * rowa[tid]
                      + red[tid] + red[64 + tid] + red[128 + tid] + red[192 + tid];
        // Rescale O by alpha
        for (int i = tid; i < 64 * 32; i += 256) {
            int r = i >> 5, c4 = (i & 31) * 4;
            float a = rowa[r];
            float4 o4 = *(float4*)(Os + r * AO_LD + c4);
            o4.x *= a; o4.y *= a; o4.z *= a; o4.w *= a;
            *(float4*)(Os + r * AO_LD + c4) = o4;
        }
        __syncthreads();

        // O += P V
        {
            wmma::fragment<wmma::accumulator, 16, 16, 16, float> oacc[4];
#pragma unroll
            for (int j = 0; j < 4; j++)
                wmma::load_matrix_sync(oacc[j], Os + wr * 16 * AO_LD + wc * 64 + j * 16,
                                       AO_LD, wmma::mem_row_major);
#pragma unroll
            for (int kk = 0; kk < 64; kk += 16) {
                wmma::fragment<wmma::matrix_a, 16, 16, 16, __half, wmma::row_major> af;
                wmma::load_matrix_sync(af, Ps + wr * 16 * AP_LD + kk, AP_LD);
#pragma unroll
                for (int j = 0; j < 4; j++) {
                    wmma::fragment<wmma::matrix_b, 16, 16, 16, __half, wmma::row_major> bf;
                    wmma::load_matrix_sync(bf, Vt + kk * AQ_LD + wc * 64 + j * 16, AQ_LD);
                    wmma::mma_sync(oacc[j], af, bf, oacc[j]);
                }
            }
#pragma unroll
            for (int j = 0; j < 4; j++)
                wmma::store_matrix_sync(Os + wr * 16 * AO_LD + wc * 64 + j * 16, oacc[j],
                                        AO_LD, wmma::mem_row_major);
        }
        __syncthreads();
    }

    // Epilogue: normalize, sigmoid-gate, write fp16
    for (int i = tid; i < 64 * 32; i += 256) {
        int r = i >> 5, c4 = (i & 31) * 4;
        int s = qt * 64 + r;
        float inv = 1.0f / rowl[r];
        float4 g4 = *(const float4*)(Gb + (size_t)s * QKVW + c4);
        float4 o4 = *(float4*)(Os + r * AO_LD + c4);
        size_t idx = ((size_t)b * SEQLEN + s) * HID + h * HD + c4;
        ao[idx]     = __float2half(o4.x * inv * (1.0f / (1.0f + __expf(-g4.x))));
        ao[idx + 1] = __float2half(o4.y * inv * (1.0f / (1.0f + __expf(-g4.y))));
        ao[idx + 2] = __float2half(o4.z * inv * (1.0f / (1.0f + __expf(-g4.z))));
        ao[idx + 3] = __float2half(o4.w * inv * (1.0f / (1.0f + __expf(-g4.w))));
    }
}

// ---------------------------------------------------------------------------
extern "C" void kernel_launch(void* const* d_in, const int* in_sizes, int n_in,
                              void* d_out, int out_size)
{
    const float* x     = (const float*)d_in[0];
    const int*   amask = (const int*)  d_in[1];
    const int*   pos   = (const int*)  d_in[2];
    const float* Wq    = (const float*)d_in[3];
    const float* Wk    = (const float*)d_in[4];
    const float* Wv    = (const float*)d_in[5];
    const float* Wo    = (const float*)d_in[6];
    const float* qnw   = (const float*)d_in[7];
    const float* knw   = (const float*)d_in[8];
    float* out = (float*)d_out;

    void *p_qkv, *p_xh, *p_bt, *p_bo, *p_qh, *p_kh, *p_vh, *p_ah;
    cudaGetSymbolAddress(&p_qkv, g_qkv);
    cudaGetSymbolAddress(&p_xh,  g_xh);
    cudaGetSymbolAddress(&p_bt,  g_bt);
    cudaGetSymbolAddress(&p_bo,  g_bo);
    cudaGetSymbolAddress(&p_qh,  g_qh);
    cudaGetSymbolAddress(&p_kh,  g_kh);
    cudaGetSymbolAddress(&p_vh,  g_vh);
    cudaGetSymbolAddress(&p_ah,  g_ah);
    float*  qkv = (float*)p_qkv;
    __half* xh  = (__half*)p_xh;
    __half* bt  = (__half*)p_bt;
    __half* bo  = (__half*)p_bo;
    __half* qh  = (__half*)p_qh;
    __half* kh  = (__half*)p_kh;
    __half* vh  = (__half*)p_vh;
    __half* ah  = (__half*)p_ah;

    // 0) Prep: convert x; transpose+convert weights
    conv_x<<<1184, 256>>>(x, xh, T_TOK * HID);
    tconv<<<dim3(4096 / 32, KDIM / 32), dim3(32, 8)>>>(Wq, bt, 4096);
    tconv<<<dim3(1024 / 32, KDIM / 32), dim3(32, 8)>>>(Wk, bt + (size_t)4096 * KDIM, 1024);
    tconv<<<dim3(1024 / 32, KDIM / 32), dim3(32, 8)>>>(Wv, bt + (size_t)5120 * KDIM, 1024);
    tconv<<<dim3(2048 / 32, KDIM / 32), dim3(32, 8)>>>(Wo, bo, 2048);

    // 1) QKV+gate projection -> g_qkv fp32 [4096][6144]
    cudaFuncSetAttribute(gemm_h1, cudaFuncAttributeMaxDynamicSharedMemorySize, G_TOTAL);
    gemm_h1<<<dim3(48, 32), 128, G_TOTAL>>>(xh, bt, qkv, QKVW);

    // 2) RMSNorm + RoPE -> fp16 q/k/v
    normrope_kernel<<<dim3(T_TOK, 32), 128>>>(qkv, qh, kh, vh, qnw, knw, pos);

    // 3) fp16 flash attention + sigmoid gate -> fp16
    cudaFuncSetAttribute(attn_h, cudaFuncAttributeMaxDynamicSharedMemorySize, ATT_SMEM);
    attn_h<<<dim3(SEQLEN / 64, NQH, 2), 256, ATT_SMEM>>>(qh, kh, vh, qkv, amask, ah);

    // 4) Output projection -> d_out fp32
    gemm_h1<<<dim3(16, 32), 128, G_TOTAL>>>(ah, bo, out, HID);
}